// round 1
// baseline (speedup 1.0000x reference)
#include <cuda_runtime.h>
#include <cstddef>

// ---------------- constants ----------------
#define BATCH 64
#define NVARS 50
#define NHID 256
#define NIN 64
#define NEDGE 2450      // 50*49
#define SEN 49

// scratch layout (floats)
#define HR_OFF   ((size_t)0)          // 3 * 3200 * 256
#define HS_OFF   ((size_t)2457600)
#define AGG_OFF  ((size_t)4915200)    // 3200*256
#define TR_OFF   ((size_t)5734400)
#define TI_OFF   ((size_t)6553600)
#define TN_OFF   ((size_t)7372800)
#define HHB_OFF  ((size_t)8192000)
#define P1_OFF   ((size_t)9011200)
#define W2T_OFF  ((size_t)9830400)    // 3 * 256 * 256
#define SCRATCH_TOTAL ((size_t)10027008)

__device__ float g_scratch[SCRATCH_TOTAL];

static __device__ __forceinline__ float tanha(float x) {
    float y; asm("tanh.approx.f32 %0, %1;" : "=f"(y) : "f"(x)); return y;
}
static __device__ __forceinline__ float sigm(float x) {
    return 1.0f / (1.0f + __expf(-x));
}

// ---------------- zero kernel ----------------
__global__ void zero_kernel(float* p, int n) {
    for (int i = blockIdx.x * blockDim.x + threadIdx.x; i < n; i += gridDim.x * blockDim.x)
        p[i] = 0.0f;
}

// ---------------- W2 transpose: W2T[k][h][g] = fc2w[k+1][g][h] ----------------
__global__ void transpose_w2(const float* __restrict__ fc2w) {
    int t = blockIdx.x * blockDim.x + threadIdx.x;
    if (t >= 3 * 256 * 256) return;
    int k = t / 65536;
    int rem = t - k * 65536;
    int h = rem >> 8;
    int g = rem & 255;
    g_scratch[W2T_OFF + (size_t)k * 65536 + (size_t)h * 256 + g] =
        fc2w[(size_t)(k + 1) * 65536 + (size_t)g * 256 + h];
}

// ---------------- generic NT GEMM: C = act(A[MxK] @ B[NxK]^T + bias + D) ----------------
// BM=64, BN=64, BK=16, 128 threads, thread tile 8x4
// ACT: 0 none, 2 sigmoid, 3 relu
template <int ACT>
__global__ void __launch_bounds__(128) gemm_nt(
    const float* __restrict__ A, int lda,
    const float* __restrict__ Bw, int ldb,
    const float* __restrict__ bias,
    const float* __restrict__ Dadd,
    float* __restrict__ C,
    int M, int N, int K)
{
    __shared__ float As[16][65];
    __shared__ float Bs[16][68];   // row stride 68*4=272B, 16B aligned for float4 reads

    int t = threadIdx.x;
    int bm = blockIdx.x * 64;
    int bn = blockIdx.y * 64;
    int ty = t >> 4;       // 0..7  -> rows ty*8 .. ty*8+7
    int tx = t & 15;       // 0..15 -> cols tx*4 .. tx*4+3

    float acc[8][4];
#pragma unroll
    for (int m = 0; m < 8; ++m)
#pragma unroll
        for (int n = 0; n < 4; ++n) acc[m][n] = 0.0f;

    for (int kb = 0; kb < K; kb += 16) {
        __syncthreads();
#pragma unroll
        for (int j = 0; j < 2; ++j) {
            int f4 = t * 2 + j;            // 0..255
            int row = f4 >> 2;             // 0..63
            int c = f4 & 3;                // 0..3
            float4 av = *(const float4*)&A[(size_t)(bm + row) * lda + kb + c * 4];
            As[c * 4 + 0][row] = av.x; As[c * 4 + 1][row] = av.y;
            As[c * 4 + 2][row] = av.z; As[c * 4 + 3][row] = av.w;
            float4 bv = *(const float4*)&Bw[(size_t)(bn + row) * ldb + kb + c * 4];
            Bs[c * 4 + 0][row] = bv.x; Bs[c * 4 + 1][row] = bv.y;
            Bs[c * 4 + 2][row] = bv.z; Bs[c * 4 + 3][row] = bv.w;
        }
        __syncthreads();
#pragma unroll
        for (int k2 = 0; k2 < 16; ++k2) {
            float a[8];
#pragma unroll
            for (int m = 0; m < 8; ++m) a[m] = As[k2][ty * 8 + m];
            float4 bv = *(const float4*)&Bs[k2][tx * 4];
            float b4[4] = {bv.x, bv.y, bv.z, bv.w};
#pragma unroll
            for (int m = 0; m < 8; ++m)
#pragma unroll
                for (int n = 0; n < 4; ++n) acc[m][n] += a[m] * b4[n];
        }
    }

#pragma unroll
    for (int m = 0; m < 8; ++m) {
        int row = bm + ty * 8 + m;
#pragma unroll
        for (int n = 0; n < 4; ++n) {
            int col = bn + tx * 4 + n;
            float v = acc[m][n];
            if (bias) v += bias[col];
            if (Dadd) v += Dadd[(size_t)row * N + col];
            if (ACT == 2) v = sigm(v);
            if (ACT == 3) v = fmaxf(v, 0.0f);
            C[(size_t)row * N + col] = v;
        }
    }
}

// ---------------- fused edge fc2 + tanh + weight + scatter-reduce ----------------
// grid: x = r*7 + sender_octet(7 heptets), y = batch_octet(8), z = edge-type idx (kt = z+1)
// block: 256 threads. Rows = 8 batches x 7 senders = 56. N = 256. K = 256.
// Thread tile: 7 rows (= 7 senders of ONE batch) x 8 cols -> in-thread sender
// reduction, then 8 atomics per thread into agg.
__global__ void __launch_bounds__(256, 2) edge_kernel(
    const float* __restrict__ edges, const float* __restrict__ fc2b)
{
    __shared__ float Xs[16][57];
    __shared__ float Ws[16][260];  // row stride 260*4=1040B, 16B aligned

    int bx = blockIdx.x;
    int r = bx / 7;
    int so = bx - r * 7;
    int bo = blockIdx.y;
    int kk = blockIdx.z;            // 0..2
    int kt = kk + 1;

    const float* HR = g_scratch + HR_OFF + (size_t)kk * BATCH * NVARS * NHID;
    const float* HS = g_scratch + HS_OFF + (size_t)kk * BATCH * NVARS * NHID;
    const float* W2Tk = g_scratch + W2T_OFF + (size_t)kk * NHID * NHID;

    int t = threadIdx.x;
    int rg = t >> 5;                // 0..7 = local batch
    int c0 = (t & 31) * 8;          // column base

    // X loader mapping (threads 0..223)
    int lrow = t >> 2;
    int lc4 = t & 3;
    size_t hrbase = 0, hsbase = 0;
    if (t < 224) {
        int b_l = lrow / 7;
        int s_l = lrow - b_l * 7;
        int b = bo * 8 + b_l;
        int sg = so * 7 + s_l;
        int i = sg + (sg >= r ? 1 : 0);
        hrbase = ((size_t)b * NVARS + r) * NHID;
        hsbase = ((size_t)b * NVARS + i) * NHID;
    }

    float acc[7][8];
#pragma unroll
    for (int s = 0; s < 7; ++s)
#pragma unroll
        for (int j = 0; j < 8; ++j) acc[s][j] = 0.0f;

    for (int kb = 0; kb < 16; ++kb) {
        __syncthreads();
        if (t < 224) {
            float4 a = *(const float4*)&HR[hrbase + kb * 16 + lc4 * 4];
            float4 s4 = *(const float4*)&HS[hsbase + kb * 16 + lc4 * 4];
            Xs[lc4 * 4 + 0][lrow] = tanha(a.x + s4.x);
            Xs[lc4 * 4 + 1][lrow] = tanha(a.y + s4.y);
            Xs[lc4 * 4 + 2][lrow] = tanha(a.z + s4.z);
            Xs[lc4 * 4 + 3][lrow] = tanha(a.w + s4.w);
        }
#pragma unroll
        for (int j = 0; j < 4; ++j) {
            int f4 = t + j * 256;          // 0..1023
            int row = f4 >> 6;             // 0..15
            int col = (f4 & 63) * 4;       // 0..252
            *(float4*)&Ws[row][col] = *(const float4*)&W2Tk[(size_t)kb * 4096 + (size_t)f4 * 4];
        }
        __syncthreads();
#pragma unroll
        for (int k2 = 0; k2 < 16; ++k2) {
            float xf[7];
#pragma unroll
            for (int s = 0; s < 7; ++s) xf[s] = Xs[k2][rg * 7 + s];
            float4 w0 = *(const float4*)&Ws[k2][c0];
            float4 w1 = *(const float4*)&Ws[k2][c0 + 4];
            float wf[8] = {w0.x, w0.y, w0.z, w0.w, w1.x, w1.y, w1.z, w1.w};
#pragma unroll
            for (int s = 0; s < 7; ++s)
#pragma unroll
                for (int j = 0; j < 8; ++j) acc[s][j] += xf[s] * wf[j];
        }
    }

    // epilogue
    int b = bo * 8 + rg;
    float4 b0 = *(const float4*)&fc2b[kt * 256 + c0];
    float4 b1 = *(const float4*)&fc2b[kt * 256 + c0 + 4];
    float bias[8] = {b0.x, b0.y, b0.z, b0.w, b1.x, b1.y, b1.z, b1.w};

    float sum[8];
#pragma unroll
    for (int j = 0; j < 8; ++j) sum[j] = 0.0f;

#pragma unroll
    for (int s = 0; s < 7; ++s) {
        int sg = so * 7 + s;
        int i = sg + (sg >= r ? 1 : 0);
        int e = i * 49 + r - (i < r ? 1 : 0);
        float w = __ldg(&edges[((size_t)b * NEDGE + e) * 4 + kt]) * (1.0f / 147.0f);
#pragma unroll
        for (int j = 0; j < 8; ++j)
            sum[j] += tanha(acc[s][j] + bias[j]) * w;
    }

    float* aggp = g_scratch + AGG_OFF + ((size_t)b * NVARS + r) * NHID + c0;
#pragma unroll
    for (int j = 0; j < 8; ++j) atomicAdd(&aggp[j], sum[j]);
}

// ---------------- GRU elementwise combine ----------------
__global__ void gru_combine(const float* __restrict__ hidden, float* __restrict__ new_hidden) {
    const float* tr = g_scratch + TR_OFF;   // r (post-sigmoid)
    const float* ti = g_scratch + TI_OFF;   // i (post-sigmoid)
    const float* tn = g_scratch + TN_OFF;   // inp_n
    const float* hb = g_scratch + HHB_OFF;  // agg @ hh_w^T
    int total = BATCH * NVARS * NHID;
    for (int idx = blockIdx.x * blockDim.x + threadIdx.x; idx < total; idx += gridDim.x * blockDim.x) {
        float i_ = ti[idx];
        float n_ = tanha(tn[idx] + tr[idx] * hb[idx]);
        new_hidden[idx] = (1.0f - i_) * n_ + i_ * hidden[idx];
    }
}

// ---------------- launch ----------------
extern "C" void kernel_launch(void* const* d_in, const int* in_sizes, int n_in,
                              void* d_out, int out_size) {
    const float* inputs = (const float*)d_in[0];   // [64,50,64]
    const float* hidden = (const float*)d_in[1];   // [64,50,256]
    const float* edges  = (const float*)d_in[2];   // [64,2450,4]
    const float* fc1w   = (const float*)d_in[3];   // [4,256,512]
    const float* fc1b   = (const float*)d_in[4];   // [4,256]
    const float* fc2w   = (const float*)d_in[5];   // [4,256,256]
    const float* fc2b   = (const float*)d_in[6];   // [4,256]
    const float* hr_w   = (const float*)d_in[7];
    const float* hi_w   = (const float*)d_in[8];
    const float* hh_w   = (const float*)d_in[9];
    const float* ir_w   = (const float*)d_in[10];
    const float* ir_b   = (const float*)d_in[11];
    const float* ii_w   = (const float*)d_in[12];
    const float* ii_b   = (const float*)d_in[13];
    const float* in_w   = (const float*)d_in[14];
    const float* in_b   = (const float*)d_in[15];
    const float* of1_w  = (const float*)d_in[16];
    const float* of1_b  = (const float*)d_in[17];
    const float* of2_w  = (const float*)d_in[18];
    const float* of2_b  = (const float*)d_in[19];
    const float* mu_w   = (const float*)d_in[20];  // [64,256]
    const float* mu_b   = (const float*)d_in[21];  // [64]

    float* out = (float*)d_out;
    float* out_mu   = out;                 // [64,50,64]
    float* out_nh   = out + 204800;        // [64,50,256]
    float* out_pred = out + 1024000;       // [64,50,256]

    float* S = nullptr;
    cudaGetSymbolAddress((void**)&S, g_scratch);

    const int M = BATCH * NVARS;  // 3200

    // zero agg
    zero_kernel<<<256, 256>>>(S + AGG_OFF, M * NHID);
    // transpose fc2 weights for edge types 1..3
    transpose_w2<<<(3 * 65536 + 255) / 256, 256>>>(fc2w);

    // node-side fc1 factorization: Hr_k = hidden @ Wr_k^T + b1_k ; Hs_k = hidden @ Ws_k^T
    for (int kk = 0; kk < 3; ++kk) {
        int kt = kk + 1;
        gemm_nt<0><<<dim3(M / 64, 4), 128>>>(
            hidden, NHID, fc1w + (size_t)kt * 256 * 512, 512,
            fc1b + kt * 256, nullptr, S + HR_OFF + (size_t)kk * M * NHID, M, NHID, NHID);
        gemm_nt<0><<<dim3(M / 64, 4), 128>>>(
            hidden, NHID, fc1w + (size_t)kt * 256 * 512 + 256, 512,
            nullptr, nullptr, S + HS_OFF + (size_t)kk * M * NHID, M, NHID, NHID);
    }

    // fused edge fc2 + aggregate
    edge_kernel<<<dim3(NVARS * 7, 8, 3), 256>>>(edges, fc2b);

    // input projections
    gemm_nt<0><<<dim3(M / 64, 4), 128>>>(inputs, NIN, ir_w, NIN, ir_b, nullptr, S + TR_OFF, M, NHID, NIN);
    gemm_nt<0><<<dim3(M / 64, 4), 128>>>(inputs, NIN, ii_w, NIN, ii_b, nullptr, S + TI_OFF, M, NHID, NIN);
    gemm_nt<0><<<dim3(M / 64, 4), 128>>>(inputs, NIN, in_w, NIN, in_b, nullptr, S + TN_OFF, M, NHID, NIN);

    // gates: r = sigmoid(agg@hr^T + inp_r), i = sigmoid(agg@hi^T + inp_i), hhb = agg@hh^T
    gemm_nt<2><<<dim3(M / 64, 4), 128>>>(S + AGG_OFF, NHID, hr_w, NHID, nullptr, S + TR_OFF, S + TR_OFF, M, NHID, NHID);
    gemm_nt<2><<<dim3(M / 64, 4), 128>>>(S + AGG_OFF, NHID, hi_w, NHID, nullptr, S + TI_OFF, S + TI_OFF, M, NHID, NHID);
    gemm_nt<0><<<dim3(M / 64, 4), 128>>>(S + AGG_OFF, NHID, hh_w, NHID, nullptr, nullptr, S + HHB_OFF, M, NHID, NHID);

    // new_hidden
    gru_combine<<<256, 256>>>(hidden, out_nh);

    // output head
    gemm_nt<3><<<dim3(M / 64, 4), 128>>>(out_nh, NHID, of1_w, NHID, of1_b, nullptr, S + P1_OFF, M, NHID, NHID);
    gemm_nt<3><<<dim3(M / 64, 4), 128>>>(S + P1_OFF, NHID, of2_w, NHID, of2_b, nullptr, out_pred, M, NHID, NHID);
    gemm_nt<0><<<dim3(M / 64, 1), 128>>>(out_pred, NHID, mu_w, NHID, mu_b, nullptr, out_mu, M, NIN, NHID);
}

// round 5
// speedup vs baseline: 1.3832x; 1.3832x over previous
#include <cuda_runtime.h>
#include <cstdint>
#include <cstddef>

// ---------------- constants ----------------
#define BATCH 64
#define NVARS 50
#define NHID 256
#define NIN 64
#define NEDGE 2450

// scratch layout (floats)
#define HR_OFF   ((size_t)0)          // 3 * 3200 * 256
#define HS_OFF   ((size_t)2457600)
#define AGG_OFF  ((size_t)4915200)    // 3200*256
#define TR_OFF   ((size_t)5734400)
#define TI_OFF   ((size_t)6553600)
#define TN_OFF   ((size_t)7372800)
#define HHB_OFF  ((size_t)8192000)
#define P1_OFF   ((size_t)9011200)
#define SCRATCH_TOTAL ((size_t)9830400)

__device__ float g_scratch[SCRATCH_TOTAL];

static __device__ __forceinline__ float tanha(float x) {
    float y; asm("tanh.approx.f32 %0, %1;" : "=f"(y) : "f"(x)); return y;
}
static __device__ __forceinline__ float sigm(float x) {
    return 1.0f / (1.0f + __expf(-x));
}
// tf32 cvt: destination must be a .b32 register
static __device__ __forceinline__ float cvt_tf32(float x) {
    uint32_t y; asm("cvt.rna.tf32.f32 %0, %1;" : "=r"(y) : "f"(x));
    return __uint_as_float(y);
}

// m16n8k8 tf32 mma: D += A(16x8 row) * B(8x8 col)
static __device__ __forceinline__ void mma_tf32(float* d, const float4 a, float b0, float b1) {
    asm volatile(
        "mma.sync.aligned.m16n8k8.row.col.f32.tf32.tf32.f32 "
        "{%0,%1,%2,%3}, {%4,%5,%6,%7}, {%8,%9}, {%0,%1,%2,%3};"
        : "+f"(d[0]), "+f"(d[1]), "+f"(d[2]), "+f"(d[3])
        : "r"(__float_as_uint(a.x)), "r"(__float_as_uint(a.y)),
          "r"(__float_as_uint(a.z)), "r"(__float_as_uint(a.w)),
          "r"(__float_as_uint(b0)), "r"(__float_as_uint(b1)));
}

// ---------------- zero kernel ----------------
__global__ void zero_kernel(float* p, int n) {
    for (int i = blockIdx.x * blockDim.x + threadIdx.x; i < n; i += gridDim.x * blockDim.x)
        p[i] = 0.0f;
}

// ---------------- generic NT GEMM core ----------------
// BM=64, BN=64, BK=16, 128 threads, thread tile 8x4. act: 0 none, 2 sigmoid, 3 relu
static __device__ __forceinline__ void gemm_core(
    const float* __restrict__ A, int lda,
    const float* __restrict__ Bw, int ldb,
    const float* __restrict__ bias,
    const float* __restrict__ Dadd,
    float* __restrict__ C,
    int N, int K, int bm, int bn, int act)
{
    __shared__ float As[16][65];
    __shared__ float Bs[16][68];

    int t = threadIdx.x;
    int ty = t >> 4;
    int tx = t & 15;

    float acc[8][4];
#pragma unroll
    for (int m = 0; m < 8; ++m)
#pragma unroll
        for (int n = 0; n < 4; ++n) acc[m][n] = 0.0f;

    for (int kb = 0; kb < K; kb += 16) {
        __syncthreads();
#pragma unroll
        for (int j = 0; j < 2; ++j) {
            int f4 = t * 2 + j;
            int row = f4 >> 2;
            int c = f4 & 3;
            float4 av = *(const float4*)&A[(size_t)(bm + row) * lda + kb + c * 4];
            As[c * 4 + 0][row] = av.x; As[c * 4 + 1][row] = av.y;
            As[c * 4 + 2][row] = av.z; As[c * 4 + 3][row] = av.w;
            float4 bv = *(const float4*)&Bw[(size_t)(bn + row) * ldb + kb + c * 4];
            Bs[c * 4 + 0][row] = bv.x; Bs[c * 4 + 1][row] = bv.y;
            Bs[c * 4 + 2][row] = bv.z; Bs[c * 4 + 3][row] = bv.w;
        }
        __syncthreads();
#pragma unroll
        for (int k2 = 0; k2 < 16; ++k2) {
            float a[8];
#pragma unroll
            for (int m = 0; m < 8; ++m) a[m] = As[k2][ty * 8 + m];
            float4 bv = *(const float4*)&Bs[k2][tx * 4];
            float b4[4] = {bv.x, bv.y, bv.z, bv.w};
#pragma unroll
            for (int m = 0; m < 8; ++m)
#pragma unroll
                for (int n = 0; n < 4; ++n) acc[m][n] += a[m] * b4[n];
        }
    }

#pragma unroll
    for (int m = 0; m < 8; ++m) {
        int row = bm + ty * 8 + m;
#pragma unroll
        for (int n = 0; n < 4; ++n) {
            int col = bn + tx * 4 + n;
            float v = acc[m][n];
            if (bias) v += bias[col];
            if (Dadd) v += Dadd[(size_t)row * N + col];
            if (act == 2) v = sigm(v);
            else if (act == 3) v = fmaxf(v, 0.0f);
            C[(size_t)row * N + col] = v;
        }
    }
}

template <int ACT>
__global__ void __launch_bounds__(128) gemm_nt(
    const float* __restrict__ A, int lda,
    const float* __restrict__ Bw, int ldb,
    const float* __restrict__ bias,
    const float* __restrict__ Dadd,
    float* __restrict__ C, int N, int K)
{
    gemm_core(A, lda, Bw, ldb, bias, Dadd, C, N, K, blockIdx.x * 64, blockIdx.y * 64, ACT);
}

// all six fc1 half-GEMMs in one launch: z = kk*2 + half
__global__ void __launch_bounds__(128) fc1_all(
    const float* __restrict__ hidden, const float* __restrict__ fc1w, const float* __restrict__ fc1b)
{
    int z = blockIdx.z;
    int kk = z >> 1, half = z & 1, kt = kk + 1;
    const float* Bw = fc1w + (size_t)kt * 256 * 512 + half * 256;
    const float* bias = half ? nullptr : fc1b + kt * 256;
    float* C = g_scratch + (half ? HS_OFF : HR_OFF) + (size_t)kk * 819200;
    gemm_core(hidden, NHID, Bw, 512, bias, nullptr, C, NHID, NHID, blockIdx.x * 64, blockIdx.y * 64, 0);
}

// three input projections in one launch
__global__ void __launch_bounds__(128) proj_all(
    const float* __restrict__ inputs,
    const float* __restrict__ w0, const float* __restrict__ w1, const float* __restrict__ w2,
    const float* __restrict__ b0, const float* __restrict__ b1, const float* __restrict__ b2)
{
    int z = blockIdx.z;
    const float* w = (z == 0) ? w0 : (z == 1) ? w1 : w2;
    const float* b = (z == 0) ? b0 : (z == 1) ? b1 : b2;
    float* C = g_scratch + ((z == 0) ? TR_OFF : (z == 1) ? TI_OFF : TN_OFF);
    gemm_core(inputs, NIN, w, NIN, b, nullptr, C, NHID, NIN, blockIdx.x * 64, blockIdx.y * 64, 0);
}

// three gate GEMMs in one launch
__global__ void __launch_bounds__(128) gate_all(
    const float* __restrict__ hr_w, const float* __restrict__ hi_w, const float* __restrict__ hh_w)
{
    int z = blockIdx.z;
    const float* A = g_scratch + AGG_OFF;
    const float* w = (z == 0) ? hr_w : (z == 1) ? hi_w : hh_w;
    const float* D = (z == 0) ? g_scratch + TR_OFF : (z == 1) ? g_scratch + TI_OFF : nullptr;
    float* C = (z == 0) ? g_scratch + TR_OFF : (z == 1) ? g_scratch + TI_OFF : g_scratch + HHB_OFF;
    int act = (z < 2) ? 2 : 0;
    gemm_core(A, NHID, w, NHID, nullptr, D, C, NHID, NHID, blockIdx.x * 64, blockIdx.y * 64, act);
}

// ---------------- tf32 mma.sync edge kernel ----------------
// grid (25, 50, 6): x = m-tile (128 rows g = b*50+i), y = receiver r,
// z: kk = z>>1 (edge type kt=kk+1), nh = z&1 (N half, 128 cols).
// X[row,k] = tf32(tanh(HR[b,r,k] + HS[b,i,k])) and W[n,k] are generated per
// 32-wide k-chunk directly into mma-fragment-ordered smem; 8 warps (4Mx2N)
// run m16n8k8 tf32 mma; epilogue: tanh(D+b2)*edge_w, segmented butterfly
// row-reduction, atomics into agg.
__global__ void __launch_bounds__(256, 2) edge_mma(
    const float* __restrict__ edges,
    const float* __restrict__ fc2w,
    const float* __restrict__ fc2b)
{
    // As[mtile(8)][kstep(4)][lane(32)][reg(4)]
    __shared__ float As_s[8 * 4 * 32 * 4];
    // Bs[ntile(16)][kpair(2)][lane(32)][4 = b0e,b1e,b0o,b1o]
    __shared__ float Bs_s[16 * 2 * 32 * 4];
    __shared__ float biasS[256];

    int t = threadIdx.x;
    int wid = t >> 5, lid = t & 31;
    int m0 = blockIdx.x * 128;
    int r = blockIdx.y;
    int kk = blockIdx.z >> 1, nh = blockIdx.z & 1;
    int kt = kk + 1;

    const float* HR = g_scratch + HR_OFF + (size_t)kk * 819200;
    const float* HS = g_scratch + HS_OFF + (size_t)kk * 819200;
    const float* W2 = fc2w + (size_t)kt * 65536;   // [g][h], K-major

    biasS[t] = fc2b[kt * 256 + t];

    // ---- generator indexing (fixed per thread) ----
    // X: row = t>>1 (0..127), hc = t&1 selects k-half (16 cols)
    int grow = t >> 1;
    int hc = t & 1;
    int gg = m0 + grow;
    int gb = gg / 50, gi = gg - gb * 50;
    uint32_t hr_base = (uint32_t)(gb * 50 + r) * 256 + hc * 16;
    uint32_t hs_base = (uint32_t)(gb * 50 + gi) * 256 + hc * 16;
    uint32_t w_base  = (uint32_t)(nh * 128 + grow) * 256 + hc * 16;

    int rl = grow & 15, mtile = grow >> 4;
    int nq = grow & 7, ntile = grow >> 3;
    // per-j STS bases (j = 0..3, kl0 = hc*16 + j*4)
    // PTX m16n8k8 tf32 A fragment: a0=(g,t), a1=(g+8,t), a2=(g,t+4), a3=(g+8,t+4)
    //   => reg = row_hi + 2*k_hi
    uint32_t a_sts[4], b_sts[4];
#pragma unroll
    for (int j = 0; j < 4; ++j) {
        int kl0 = hc * 16 + j * 4;
        int kstep = kl0 >> 3;
        int areg = (rl >> 3) + (((kl0 & 7) >> 2) << 1);
        a_sts[j] = ((uint32_t)(mtile * 4 + kstep) * 32 + (rl & 7) * 4) * 4 + areg;
        int kpair = kstep >> 1, pidx = kstep & 1;
        int breg = ((kl0 & 7) >> 2) + (pidx << 1);
        b_sts[j] = ((uint32_t)(ntile * 2 + kpair) * 32 + nq * 4) * 4 + breg;
    }

    // ---- compute indexing ----
    int mw = wid >> 1, nw = wid & 1;     // 4 m-warps x 2 n-warps

    float acc[2][8][4];
#pragma unroll
    for (int mt = 0; mt < 2; ++mt)
#pragma unroll
        for (int nt = 0; nt < 8; ++nt)
#pragma unroll
            for (int q = 0; q < 4; ++q) acc[mt][nt][q] = 0.0f;

    for (int kc = 0; kc < 8; ++kc) {
        __syncthreads();
        // generate X fragments
        {
            const float* hrp = HR + hr_base + kc * 32;
            const float* hsp = HS + hs_base + kc * 32;
#pragma unroll
            for (int j = 0; j < 4; ++j) {
                float4 a = *(const float4*)(hrp + j * 4);
                float4 s = *(const float4*)(hsp + j * 4);
                uint32_t ad = a_sts[j];
                As_s[ad]      = cvt_tf32(tanha(a.x + s.x));
                As_s[ad + 4]  = cvt_tf32(tanha(a.y + s.y));
                As_s[ad + 8]  = cvt_tf32(tanha(a.z + s.z));
                As_s[ad + 12] = cvt_tf32(tanha(a.w + s.w));
            }
            const float* wp = W2 + w_base + kc * 32;
#pragma unroll
            for (int j = 0; j < 4; ++j) {
                float4 w4 = *(const float4*)(wp + j * 4);
                uint32_t bd = b_sts[j];
                Bs_s[bd]      = cvt_tf32(w4.x);
                Bs_s[bd + 4]  = cvt_tf32(w4.y);
                Bs_s[bd + 8]  = cvt_tf32(w4.z);
                Bs_s[bd + 12] = cvt_tf32(w4.w);
            }
        }
        __syncthreads();
#pragma unroll
        for (int kp = 0; kp < 2; ++kp) {
            float4 ae0 = *(const float4*)&As_s[(((mw * 2 + 0) * 4 + kp * 2) * 32 + lid) * 4];
            float4 ae1 = *(const float4*)&As_s[(((mw * 2 + 1) * 4 + kp * 2) * 32 + lid) * 4];
            float4 ao0 = *(const float4*)&As_s[(((mw * 2 + 0) * 4 + kp * 2 + 1) * 32 + lid) * 4];
            float4 ao1 = *(const float4*)&As_s[(((mw * 2 + 1) * 4 + kp * 2 + 1) * 32 + lid) * 4];
#pragma unroll
            for (int nt = 0; nt < 8; ++nt) {
                float4 bb = *(const float4*)&Bs_s[(((nw * 8 + nt) * 2 + kp) * 32 + lid) * 4];
                mma_tf32(acc[0][nt], ae0, bb.x, bb.y);
                mma_tf32(acc[1][nt], ae1, bb.x, bb.y);
                mma_tf32(acc[0][nt], ao0, bb.z, bb.w);
                mma_tf32(acc[1][nt], ao1, bb.z, bb.w);
            }
        }
    }

    // ---- epilogue ----
    int lq = lid & 3, lr = lid >> 2;
    int base_row = mw * 32;
    int bfirst = (m0 + base_row) / 50;
    int blast = (m0 + base_row + 31) / 50;
    int has1 = (blast != bfirst);

    float wgt[4];
    int sg[4];
#pragma unroll
    for (int j = 0; j < 4; ++j) {
        int mt = j >> 1, rh = j & 1;
        int row_local = base_row + mt * 16 + rh * 8 + lr;
        int g = m0 + row_local;
        int b = g / 50, i = g - b * 50;
        sg[j] = b - bfirst;
        float w = 0.0f;
        if (i != r) {
            int e = i * 49 + r - (i < r ? 1 : 0);
            w = __ldg(&edges[((size_t)b * NEDGE + e) * 4 + kt]) * (1.0f / 147.0f);
        }
        wgt[j] = w;
    }

    float* agg0 = g_scratch + AGG_OFF + ((size_t)(bfirst * 50 + r)) * 256;

#pragma unroll
    for (int nt = 0; nt < 8; ++nt) {
        int colg = nh * 128 + nw * 64 + nt * 8 + lq * 2;
        float b0 = biasS[colg], b1 = biasS[colg + 1];
        float c0[2] = {0.0f, 0.0f}, c1[2] = {0.0f, 0.0f};
#pragma unroll
        for (int j = 0; j < 4; ++j) {
            int mt = j >> 1, rh = j & 1;
            float t0 = tanha(acc[mt][nt][rh * 2 + 0] + b0) * wgt[j];
            float t1 = tanha(acc[mt][nt][rh * 2 + 1] + b1) * wgt[j];
            if (sg[j] == 0) { c0[0] += t0; c1[0] += t1; }
            else            { c0[1] += t0; c1[1] += t1; }
        }
#pragma unroll
        for (int o = 4; o <= 16; o <<= 1) {
            c0[0] += __shfl_xor_sync(0xffffffffu, c0[0], o);
            c1[0] += __shfl_xor_sync(0xffffffffu, c1[0], o);
            if (has1) {
                c0[1] += __shfl_xor_sync(0xffffffffu, c0[1], o);
                c1[1] += __shfl_xor_sync(0xffffffffu, c1[1], o);
            }
        }
        if (lid < 4) {
            atomicAdd(&agg0[colg], c0[0]);
            atomicAdd(&agg0[colg + 1], c1[0]);
            if (has1) {
                atomicAdd(&agg0[12800 + colg], c0[1]);      // (bfirst+1)*50*256
                atomicAdd(&agg0[12800 + colg + 1], c1[1]);
            }
        }
    }
}

// ---------------- GRU elementwise combine ----------------
__global__ void gru_combine(const float* __restrict__ hidden, float* __restrict__ new_hidden) {
    const float* tr = g_scratch + TR_OFF;
    const float* ti = g_scratch + TI_OFF;
    const float* tn = g_scratch + TN_OFF;
    const float* hb = g_scratch + HHB_OFF;
    int total = BATCH * NVARS * NHID;
    for (int idx = blockIdx.x * blockDim.x + threadIdx.x; idx < total; idx += gridDim.x * blockDim.x) {
        float i_ = ti[idx];
        float n_ = tanha(tn[idx] + tr[idx] * hb[idx]);
        new_hidden[idx] = (1.0f - i_) * n_ + i_ * hidden[idx];
    }
}

// ---------------- launch ----------------
extern "C" void kernel_launch(void* const* d_in, const int* in_sizes, int n_in,
                              void* d_out, int out_size) {
    const float* inputs = (const float*)d_in[0];
    const float* hidden = (const float*)d_in[1];
    const float* edges  = (const float*)d_in[2];
    const float* fc1w   = (const float*)d_in[3];
    const float* fc1b   = (const float*)d_in[4];
    const float* fc2w   = (const float*)d_in[5];
    const float* fc2b   = (const float*)d_in[6];
    const float* hr_w   = (const float*)d_in[7];
    const float* hi_w   = (const float*)d_in[8];
    const float* hh_w   = (const float*)d_in[9];
    const float* ir_w   = (const float*)d_in[10];
    const float* ir_b   = (const float*)d_in[11];
    const float* ii_w   = (const float*)d_in[12];
    const float* ii_b   = (const float*)d_in[13];
    const float* in_w   = (const float*)d_in[14];
    const float* in_b   = (const float*)d_in[15];
    const float* of1_w  = (const float*)d_in[16];
    const float* of1_b  = (const float*)d_in[17];
    const float* of2_w  = (const float*)d_in[18];
    const float* of2_b  = (const float*)d_in[19];
    const float* mu_w   = (const float*)d_in[20];
    const float* mu_b   = (const float*)d_in[21];

    float* out = (float*)d_out;
    float* out_mu   = out;               // [64,50,64]
    float* out_nh   = out + 204800;      // [64,50,256]
    float* out_pred = out + 1024000;     // [64,50,256]

    float* S = nullptr;
    cudaGetSymbolAddress((void**)&S, g_scratch);

    const int M = BATCH * NVARS;  // 3200

    zero_kernel<<<256, 256>>>(S + AGG_OFF, M * NHID);
    fc1_all<<<dim3(M / 64, 4, 6), 128>>>(hidden, fc1w, fc1b);
    proj_all<<<dim3(M / 64, 4, 3), 128>>>(inputs, ir_w, ii_w, in_w, ir_b, ii_b, in_b);

    edge_mma<<<dim3(25, NVARS, 6), 256>>>(edges, fc2w, fc2b);

    gate_all<<<dim3(M / 64, 4, 3), 128>>>(hr_w, hi_w, hh_w);
    gru_combine<<<256, 256>>>(hidden, out_nh);

    gemm_nt<3><<<dim3(M / 64, 4), 128>>>(out_nh, NHID, of1_w, NHID, of1_b, nullptr, S + P1_OFF, NHID, NHID);
    gemm_nt<3><<<dim3(M / 64, 4), 128>>>(S + P1_OFF, NHID, of2_w, NHID, of2_b, nullptr, out_pred, NHID, NHID);
    gemm_nt<0><<<dim3(M / 64, 1), 128>>>(out_pred, NHID, mu_w, NHID, mu_b, nullptr, out_mu, NIN, NHID);
}

// round 6
// speedup vs baseline: 2.9145x; 2.1070x over previous
#include <cuda_runtime.h>
#include <cstdint>
#include <cstddef>

// ---------------- constants ----------------
#define BATCH 64
#define NVARS 50
#define NHID 256
#define NIN 64
#define NEDGE 2450

// scratch layout (floats)
#define HR_OFF   ((size_t)0)          // 3 * 3200 * 256
#define HS_OFF   ((size_t)2457600)
#define AGG_OFF  ((size_t)4915200)    // 3200*256
#define TR_OFF   ((size_t)5734400)
#define TI_OFF   ((size_t)6553600)
#define TN_OFF   ((size_t)7372800)
#define HHB_OFF  ((size_t)8192000)
#define P1_OFF   ((size_t)9011200)
#define SCRATCH_TOTAL ((size_t)9830400)

__device__ float g_scratch[SCRATCH_TOTAL];
// W fragments, bf16x2 words, layout: [kk(3)][nh(2)][chunk(8)][2048 words]
#define WF_WORDS (3 * 2 * 8 * 2048)
__device__ uint32_t g_wf[WF_WORDS];

static __device__ __forceinline__ float tanha(float x) {
    float y; asm("tanh.approx.f32 %0, %1;" : "=f"(y) : "f"(x)); return y;
}
static __device__ __forceinline__ float sigm(float x) {
    return 1.0f / (1.0f + __expf(-x));
}
// pack two fp32 -> bf16x2 word {lo, hi}
static __device__ __forceinline__ uint32_t pack_bf16(float lo, float hi) {
    uint32_t d; asm("cvt.rn.bf16x2.f32 %0, %1, %2;" : "=r"(d) : "f"(hi), "f"(lo));
    return d;
}

// m16n8k16 bf16 mma: D += A(16x16 row) * B(16x8 col)
static __device__ __forceinline__ void mma_bf16(float* d, const uint32_t* a,
                                                uint32_t b0, uint32_t b1) {
    asm volatile(
        "mma.sync.aligned.m16n8k16.row.col.f32.bf16.bf16.f32 "
        "{%0,%1,%2,%3}, {%4,%5,%6,%7}, {%8,%9}, {%0,%1,%2,%3};"
        : "+f"(d[0]), "+f"(d[1]), "+f"(d[2]), "+f"(d[3])
        : "r"(a[0]), "r"(a[1]), "r"(a[2]), "r"(a[3]), "r"(b0), "r"(b1));
}

// ---------------- zero kernel ----------------
__global__ void zero_kernel(float* p, int n) {
    for (int i = blockIdx.x * blockDim.x + threadIdx.x; i < n; i += gridDim.x * blockDim.x)
        p[i] = 0.0f;
}

// ---------------- W fragment pre-pack ----------------
// word p: lane = p&31, reg = (p>>5)&1, tile = (p>>6)&31 -> kstep = tile&1, ntile = tile>>1
// rest = p>>11: c = rest&7, nh = (rest>>3)&1, kk = rest>>4
__global__ void w2frag(const float* __restrict__ fc2w) {
    int p = blockIdx.x * 256 + threadIdx.x;
    if (p >= WF_WORDS) return;
    int lane = p & 31;
    int reg = (p >> 5) & 1;
    int tile = (p >> 6) & 31;
    int kstep = tile & 1, ntile = tile >> 1;
    int rest = p >> 11;
    int c = rest & 7;
    int nh = (rest >> 3) & 1;
    int kk = rest >> 4;
    int n = nh * 128 + ntile * 8 + (lane >> 2);
    int k = c * 32 + kstep * 16 + reg * 8 + (lane & 3) * 2;
    const float* w = fc2w + (size_t)(kk + 1) * 65536 + (size_t)n * 256 + k;
    g_wf[p] = pack_bf16(w[0], w[1]);
}

// ---------------- generic NT GEMM core (fp32 tail) ----------------
static __device__ __forceinline__ void gemm_core(
    const float* __restrict__ A, int lda,
    const float* __restrict__ Bw, int ldb,
    const float* __restrict__ bias,
    const float* __restrict__ Dadd,
    float* __restrict__ C,
    int N, int K, int bm, int bn, int act)
{
    __shared__ float As[16][65];
    __shared__ float Bs[16][68];

    int t = threadIdx.x;
    int ty = t >> 4;
    int tx = t & 15;

    float acc[8][4];
#pragma unroll
    for (int m = 0; m < 8; ++m)
#pragma unroll
        for (int n = 0; n < 4; ++n) acc[m][n] = 0.0f;

    for (int kb = 0; kb < K; kb += 16) {
        __syncthreads();
#pragma unroll
        for (int j = 0; j < 2; ++j) {
            int f4 = t * 2 + j;
            int row = f4 >> 2;
            int c = f4 & 3;
            float4 av = *(const float4*)&A[(size_t)(bm + row) * lda + kb + c * 4];
            As[c * 4 + 0][row] = av.x; As[c * 4 + 1][row] = av.y;
            As[c * 4 + 2][row] = av.z; As[c * 4 + 3][row] = av.w;
            float4 bv = *(const float4*)&Bw[(size_t)(bn + row) * ldb + kb + c * 4];
            Bs[c * 4 + 0][row] = bv.x; Bs[c * 4 + 1][row] = bv.y;
            Bs[c * 4 + 2][row] = bv.z; Bs[c * 4 + 3][row] = bv.w;
        }
        __syncthreads();
#pragma unroll
        for (int k2 = 0; k2 < 16; ++k2) {
            float a[8];
#pragma unroll
            for (int m = 0; m < 8; ++m) a[m] = As[k2][ty * 8 + m];
            float4 bv = *(const float4*)&Bs[k2][tx * 4];
            float b4[4] = {bv.x, bv.y, bv.z, bv.w};
#pragma unroll
            for (int m = 0; m < 8; ++m)
#pragma unroll
                for (int n = 0; n < 4; ++n) acc[m][n] += a[m] * b4[n];
        }
    }

#pragma unroll
    for (int m = 0; m < 8; ++m) {
        int row = bm + ty * 8 + m;
#pragma unroll
        for (int n = 0; n < 4; ++n) {
            int col = bn + tx * 4 + n;
            float v = acc[m][n];
            if (bias) v += bias[col];
            if (Dadd) v += Dadd[(size_t)row * N + col];
            if (act == 2) v = sigm(v);
            else if (act == 3) v = fmaxf(v, 0.0f);
            C[(size_t)row * N + col] = v;
        }
    }
}

template <int ACT>
__global__ void __launch_bounds__(128) gemm_nt(
    const float* __restrict__ A, int lda,
    const float* __restrict__ Bw, int ldb,
    const float* __restrict__ bias,
    const float* __restrict__ Dadd,
    float* __restrict__ C, int N, int K)
{
    gemm_core(A, lda, Bw, ldb, bias, Dadd, C, N, K, blockIdx.x * 64, blockIdx.y * 64, ACT);
}

__global__ void __launch_bounds__(128) fc1_all(
    const float* __restrict__ hidden, const float* __restrict__ fc1w, const float* __restrict__ fc1b)
{
    int z = blockIdx.z;
    int kk = z >> 1, half = z & 1, kt = kk + 1;
    const float* Bw = fc1w + (size_t)kt * 256 * 512 + half * 256;
    const float* bias = half ? nullptr : fc1b + kt * 256;
    float* C = g_scratch + (half ? HS_OFF : HR_OFF) + (size_t)kk * 819200;
    gemm_core(hidden, NHID, Bw, 512, bias, nullptr, C, NHID, NHID, blockIdx.x * 64, blockIdx.y * 64, 0);
}

__global__ void __launch_bounds__(128) proj_all(
    const float* __restrict__ inputs,
    const float* __restrict__ w0, const float* __restrict__ w1, const float* __restrict__ w2,
    const float* __restrict__ b0, const float* __restrict__ b1, const float* __restrict__ b2)
{
    int z = blockIdx.z;
    const float* w = (z == 0) ? w0 : (z == 1) ? w1 : w2;
    const float* b = (z == 0) ? b0 : (z == 1) ? b1 : b2;
    float* C = g_scratch + ((z == 0) ? TR_OFF : (z == 1) ? TI_OFF : TN_OFF);
    gemm_core(inputs, NIN, w, NIN, b, nullptr, C, NHID, NIN, blockIdx.x * 64, blockIdx.y * 64, 0);
}

__global__ void __launch_bounds__(128) gate_all(
    const float* __restrict__ hr_w, const float* __restrict__ hi_w, const float* __restrict__ hh_w)
{
    int z = blockIdx.z;
    const float* A = g_scratch + AGG_OFF;
    const float* w = (z == 0) ? hr_w : (z == 1) ? hi_w : hh_w;
    const float* D = (z == 0) ? g_scratch + TR_OFF : (z == 1) ? g_scratch + TI_OFF : nullptr;
    float* C = (z == 0) ? g_scratch + TR_OFF : (z == 1) ? g_scratch + TI_OFF : g_scratch + HHB_OFF;
    int act = (z < 2) ? 2 : 0;
    gemm_core(A, NHID, w, NHID, nullptr, D, C, NHID, NHID, blockIdx.x * 64, blockIdx.y * 64, act);
}

// ---------------- bf16 mma.sync edge kernel ----------------
// grid (25, 50, 6): x = m-tile (128 rows g = b*50+i), y = receiver r,
// z: kk = z>>1 (edge type kt=kk+1), nh = z&1 (N half, 128 cols).
// 512 threads = 16 warps (4M x 4N), warp tile M32 x N32, m16n8k16 bf16.
// Smem staging layout [tile][reg][lane] is conflict-free on both STS.128
// (generator) and LDS.32 (compute). W comes pre-packed from g_wf (pure copy).
// Double-buffered, 1 sync per 32-k chunk, register prefetch of next chunk.
__global__ void __launch_bounds__(512, 1) edge_mma(
    const float* __restrict__ edges,
    const float* __restrict__ fc2b)
{
    __shared__ uint32_t As_w[2][2048];   // [tile(16)=(mtile*2+kstep)][reg(4)][lane(32)]
    __shared__ uint32_t Bs_w[2][2048];   // [tile(32)=(ntile*2+kstep)][reg(2)][lane(32)]
    __shared__ float biasS[256];

    int t = threadIdx.x;
    int wid = t >> 5, lid = t & 31;
    int m0 = blockIdx.x * 128;
    int r = blockIdx.y;
    int kk = blockIdx.z >> 1, nh = blockIdx.z & 1;
    int kt = kk + 1;

    const float* HR = g_scratch + HR_OFF + (size_t)kk * 819200;
    const float* HS = g_scratch + HS_OFF + (size_t)kk * 819200;

    if (t < 256) biasS[t] = fc2b[kt * 256 + t];

    // ---- generator indexing ----
    int grow = t >> 2;           // 0..127 row
    int kq = t & 3;              // 8-float k group within chunk
    int kstep = kq >> 1, khalf = kq & 1;
    int gg = m0 + grow;
    int gb = gg / 50, gi = gg - gb * 50;
    uint32_t hr_base = (uint32_t)(gb * 50 + r) * 256 + kq * 8;
    uint32_t hs_base = (uint32_t)(gb * 50 + gi) * 256 + kq * 8;
    int mtile = grow >> 4, rl = grow & 15;
    uint32_t a_sts = (uint32_t)(((mtile * 2 + kstep) * 4) + (rl >> 3) + 2 * khalf) * 32
                     + (rl & 7) * 4;
    const uint32_t* wf = g_wf + ((size_t)(kk * 2 + nh) * 8) * 2048 + t * 4;

    // ---- compute indexing ----
    int mw = wid >> 2, nw = wid & 3;   // 4 m-warps x 4 n-warps

    float acc[2][4][4];
#pragma unroll
    for (int mt = 0; mt < 2; ++mt)
#pragma unroll
        for (int nt = 0; nt < 4; ++nt)
#pragma unroll
            for (int q = 0; q < 4; ++q) acc[mt][nt][q] = 0.0f;

    float4 hr0, hr1, hs0, hs1;
    uint4 wv;

#define LDG_CHUNK(c) do { \
        const float* hp = HR + hr_base + (c) * 32; \
        const float* sp = HS + hs_base + (c) * 32; \
        hr0 = *(const float4*)hp; hr1 = *(const float4*)(hp + 4); \
        hs0 = *(const float4*)sp; hs1 = *(const float4*)(sp + 4); \
        wv = *(const uint4*)(wf + (c) * 2048); \
    } while (0)

#define STS_CHUNK(st) do { \
        uint4 xa; \
        xa.x = pack_bf16(tanha(hr0.x + hs0.x), tanha(hr0.y + hs0.y)); \
        xa.y = pack_bf16(tanha(hr0.z + hs0.z), tanha(hr0.w + hs0.w)); \
        xa.z = pack_bf16(tanha(hr1.x + hs1.x), tanha(hr1.y + hs1.y)); \
        xa.w = pack_bf16(tanha(hr1.z + hs1.z), tanha(hr1.w + hs1.w)); \
        *(uint4*)&As_w[st][a_sts] = xa; \
        *(uint4*)&Bs_w[st][t * 4] = wv; \
    } while (0)

    LDG_CHUNK(0);
    STS_CHUNK(0);
    LDG_CHUNK(1);

    for (int c = 0; c < 8; ++c) {
        int st = c & 1;
        __syncthreads();
#pragma unroll
        for (int ks = 0; ks < 2; ++ks) {
            uint32_t a[2][4];
#pragma unroll
            for (int mt = 0; mt < 2; ++mt) {
                int tile = (mw * 2 + mt) * 2 + ks;
#pragma unroll
                for (int rg = 0; rg < 4; ++rg)
                    a[mt][rg] = As_w[st][(tile * 4 + rg) * 32 + lid];
            }
#pragma unroll
            for (int nt = 0; nt < 4; ++nt) {
                int tile = (nw * 4 + nt) * 2 + ks;
                uint32_t b0 = Bs_w[st][(tile * 2 + 0) * 32 + lid];
                uint32_t b1 = Bs_w[st][(tile * 2 + 1) * 32 + lid];
                mma_bf16(acc[0][nt], a[0], b0, b1);
                mma_bf16(acc[1][nt], a[1], b0, b1);
            }
        }
        if (c < 7) {
            STS_CHUNK((c + 1) & 1);
            if (c < 6) LDG_CHUNK(c + 2);
        }
    }

    // ---- epilogue: tanh(D + b2) * edge_w, segmented row-reduce, atomics ----
    int lq = lid & 3, lr = lid >> 2;
    int base_row = mw * 32;
    int bfirst = (m0 + base_row) / 50;
    int blast = (m0 + base_row + 31) / 50;
    int has1 = (blast != bfirst);

    float wgt[4];
    int sg[4];
#pragma unroll
    for (int j = 0; j < 4; ++j) {
        int mt = j >> 1, rh = j & 1;
        int row_local = base_row + mt * 16 + rh * 8 + lr;
        int g = m0 + row_local;
        int b = g / 50, i = g - b * 50;
        sg[j] = b - bfirst;
        float w = 0.0f;
        if (i != r) {
            int e = i * 49 + r - (i < r ? 1 : 0);
            w = __ldg(&edges[((size_t)b * NEDGE + e) * 4 + kt]) * (1.0f / 147.0f);
        }
        wgt[j] = w;
    }

    float* agg0 = g_scratch + AGG_OFF + ((size_t)(bfirst * 50 + r)) * 256;

#pragma unroll
    for (int nt = 0; nt < 4; ++nt) {
        int colg = nh * 128 + nw * 32 + nt * 8 + lq * 2;
        float b0 = biasS[colg], b1 = biasS[colg + 1];
        float c0[2] = {0.0f, 0.0f}, c1[2] = {0.0f, 0.0f};
#pragma unroll
        for (int j = 0; j < 4; ++j) {
            int mt = j >> 1, rh = j & 1;
            float t0 = tanha(acc[mt][nt][rh * 2 + 0] + b0) * wgt[j];
            float t1 = tanha(acc[mt][nt][rh * 2 + 1] + b1) * wgt[j];
            if (sg[j] == 0) { c0[0] += t0; c1[0] += t1; }
            else            { c0[1] += t0; c1[1] += t1; }
        }
#pragma unroll
        for (int o = 4; o <= 16; o <<= 1) {
            c0[0] += __shfl_xor_sync(0xffffffffu, c0[0], o);
            c1[0] += __shfl_xor_sync(0xffffffffu, c1[0], o);
            if (has1) {
                c0[1] += __shfl_xor_sync(0xffffffffu, c0[1], o);
                c1[1] += __shfl_xor_sync(0xffffffffu, c1[1], o);
            }
        }
        if (lid < 4) {
            atomicAdd(&agg0[colg], c0[0]);
            atomicAdd(&agg0[colg + 1], c1[0]);
            if (has1) {
                atomicAdd(&agg0[12800 + colg], c0[1]);
                atomicAdd(&agg0[12800 + colg + 1], c1[1]);
            }
        }
    }
#undef LDG_CHUNK
#undef STS_CHUNK
}

// ---------------- GRU elementwise combine ----------------
__global__ void gru_combine(const float* __restrict__ hidden, float* __restrict__ new_hidden) {
    const float* tr = g_scratch + TR_OFF;
    const float* ti = g_scratch + TI_OFF;
    const float* tn = g_scratch + TN_OFF;
    const float* hb = g_scratch + HHB_OFF;
    int total = BATCH * NVARS * NHID;
    for (int idx = blockIdx.x * blockDim.x + threadIdx.x; idx < total; idx += gridDim.x * blockDim.x) {
        float i_ = ti[idx];
        float n_ = tanha(tn[idx] + tr[idx] * hb[idx]);
        new_hidden[idx] = (1.0f - i_) * n_ + i_ * hidden[idx];
    }
}

// ---------------- launch ----------------
extern "C" void kernel_launch(void* const* d_in, const int* in_sizes, int n_in,
                              void* d_out, int out_size) {
    const float* inputs = (const float*)d_in[0];
    const float* hidden = (const float*)d_in[1];
    const float* edges  = (const float*)d_in[2];
    const float* fc1w   = (const float*)d_in[3];
    const float* fc1b   = (const float*)d_in[4];
    const float* fc2w   = (const float*)d_in[5];
    const float* fc2b   = (const float*)d_in[6];
    const float* hr_w   = (const float*)d_in[7];
    const float* hi_w   = (const float*)d_in[8];
    const float* hh_w   = (const float*)d_in[9];
    const float* ir_w   = (const float*)d_in[10];
    const float* ir_b   = (const float*)d_in[11];
    const float* ii_w   = (const float*)d_in[12];
    const float* ii_b   = (const float*)d_in[13];
    const float* in_w   = (const float*)d_in[14];
    const float* in_b   = (const float*)d_in[15];
    const float* of1_w  = (const float*)d_in[16];
    const float* of1_b  = (const float*)d_in[17];
    const float* of2_w  = (const float*)d_in[18];
    const float* of2_b  = (const float*)d_in[19];
    const float* mu_w   = (const float*)d_in[20];
    const float* mu_b   = (const float*)d_in[21];

    float* out = (float*)d_out;
    float* out_mu   = out;               // [64,50,64]
    float* out_nh   = out + 204800;      // [64,50,256]
    float* out_pred = out + 1024000;     // [64,50,256]

    float* S = nullptr;
    cudaGetSymbolAddress((void**)&S, g_scratch);

    const int M = BATCH * NVARS;  // 3200

    zero_kernel<<<256, 256>>>(S + AGG_OFF, M * NHID);
    w2frag<<<(WF_WORDS + 255) / 256, 256>>>(fc2w);
    fc1_all<<<dim3(M / 64, 4, 6), 128>>>(hidden, fc1w, fc1b);
    proj_all<<<dim3(M / 64, 4, 3), 128>>>(inputs, ir_w, ii_w, in_w, ir_b, ii_b, in_b);

    edge_mma<<<dim3(25, NVARS, 6), 512>>>(edges, fc2b);

    gate_all<<<dim3(M / 64, 4, 3), 128>>>(hr_w, hi_w, hh_w);
    gru_combine<<<256, 256>>>(hidden, out_nh);

    gemm_nt<3><<<dim3(M / 64, 4), 128>>>(out_nh, NHID, of1_w, NHID, of1_b, nullptr, S + P1_OFF, NHID, NHID);
    gemm_nt<3><<<dim3(M / 64, 4), 128>>>(S + P1_OFF, NHID, of2_w, NHID, of2_b, nullptr, out_pred, NHID, NHID);
    gemm_nt<0><<<dim3(M / 64, 1), 128>>>(out_pred, NHID, mu_w, NHID, mu_b, nullptr, out_mu, NIN, NHID);
}

// round 8
// speedup vs baseline: 3.4919x; 1.1981x over previous
#include <cuda_runtime.h>
#include <cstdint>
#include <cstddef>

// ---------------- constants ----------------
#define BATCH 64
#define NVARS 50
#define NHID 256
#define NIN 64
#define NEDGE 2450

// scratch layout (floats)
#define HR_OFF   ((size_t)0)          // 3 * 3200 * 256
#define HS_OFF   ((size_t)2457600)
#define AGG_OFF  ((size_t)4915200)    // 3200*256
#define TR_OFF   ((size_t)5734400)
#define TI_OFF   ((size_t)6553600)
#define TN_OFF   ((size_t)7372800)
#define P1_OFF   ((size_t)8192000)
#define SCRATCH_TOTAL ((size_t)9011200)

__device__ float g_scratch[SCRATCH_TOTAL];
// W fragments, bf16x2 words: [kk(3)][chunk(8)][4096 words]
#define WF_WORDS (3 * 8 * 4096)
__device__ uint32_t g_wf[WF_WORDS];

// edge_mma dynamic smem layout (uint32 words):
//   As: [2][2048], Bs: [2][4096], bias: 256 floats
#define EDGE_AS_WORDS   (2 * 2048)
#define EDGE_BS_WORDS   (2 * 4096)
#define EDGE_SMEM_BYTES ((EDGE_AS_WORDS + EDGE_BS_WORDS + 256) * 4)

static __device__ __forceinline__ float tanha(float x) {
    float y; asm("tanh.approx.f32 %0, %1;" : "=f"(y) : "f"(x)); return y;
}
static __device__ __forceinline__ float sigm(float x) {
    return 1.0f / (1.0f + __expf(-x));
}
static __device__ __forceinline__ uint32_t pack_bf16(float lo, float hi) {
    uint32_t d; asm("cvt.rn.bf16x2.f32 %0, %1, %2;" : "=r"(d) : "f"(hi), "f"(lo));
    return d;
}

// m16n8k16 bf16 mma
static __device__ __forceinline__ void mma_bf16(float* d, const uint32_t* a,
                                                uint32_t b0, uint32_t b1) {
    asm volatile(
        "mma.sync.aligned.m16n8k16.row.col.f32.bf16.bf16.f32 "
        "{%0,%1,%2,%3}, {%4,%5,%6,%7}, {%8,%9}, {%0,%1,%2,%3};"
        : "+f"(d[0]), "+f"(d[1]), "+f"(d[2]), "+f"(d[3])
        : "r"(a[0]), "r"(a[1]), "r"(a[2]), "r"(a[3]), "r"(b0), "r"(b1));
}

// ---------------- generic NT GEMM core (fp32 tail) ----------------
// BM=64, BN=64, BK=16, 128 threads, thread tile 8x4. act: 0 none, 3 relu
static __device__ __forceinline__ void gemm_core(
    const float* __restrict__ A, int lda,
    const float* __restrict__ Bw, int ldb,
    const float* __restrict__ bias,
    float* __restrict__ C,
    int N, int K, int bm, int bn, int act)
{
    __shared__ float As[16][65];
    __shared__ float Bs[16][68];

    int t = threadIdx.x;
    int ty = t >> 4;
    int tx = t & 15;

    float acc[8][4];
#pragma unroll
    for (int m = 0; m < 8; ++m)
#pragma unroll
        for (int n = 0; n < 4; ++n) acc[m][n] = 0.0f;

    for (int kb = 0; kb < K; kb += 16) {
        __syncthreads();
#pragma unroll
        for (int j = 0; j < 2; ++j) {
            int f4 = t * 2 + j;
            int row = f4 >> 2;
            int c = f4 & 3;
            float4 av = *(const float4*)&A[(size_t)(bm + row) * lda + kb + c * 4];
            As[c * 4 + 0][row] = av.x; As[c * 4 + 1][row] = av.y;
            As[c * 4 + 2][row] = av.z; As[c * 4 + 3][row] = av.w;
            float4 bv = *(const float4*)&Bw[(size_t)(bn + row) * ldb + kb + c * 4];
            Bs[c * 4 + 0][row] = bv.x; Bs[c * 4 + 1][row] = bv.y;
            Bs[c * 4 + 2][row] = bv.z; Bs[c * 4 + 3][row] = bv.w;
        }
        __syncthreads();
#pragma unroll
        for (int k2 = 0; k2 < 16; ++k2) {
            float a[8];
#pragma unroll
            for (int m = 0; m < 8; ++m) a[m] = As[k2][ty * 8 + m];
            float4 bv = *(const float4*)&Bs[k2][tx * 4];
            float b4[4] = {bv.x, bv.y, bv.z, bv.w};
#pragma unroll
            for (int m = 0; m < 8; ++m)
#pragma unroll
                for (int n = 0; n < 4; ++n) acc[m][n] += a[m] * b4[n];
        }
    }

#pragma unroll
    for (int m = 0; m < 8; ++m) {
        int row = bm + ty * 8 + m;
#pragma unroll
        for (int n = 0; n < 4; ++n) {
            int col = bn + tx * 4 + n;
            float v = acc[m][n];
            if (bias) v += bias[col];
            if (act == 3) v = fmaxf(v, 0.0f);
            C[(size_t)row * N + col] = v;
        }
    }
}

template <int ACT>
__global__ void __launch_bounds__(128) gemm_nt(
    const float* __restrict__ A, int lda,
    const float* __restrict__ Bw, int ldb,
    const float* __restrict__ bias,
    float* __restrict__ C, int N, int K)
{
    gemm_core(A, lda, Bw, ldb, bias, C, N, K, blockIdx.x * 64, blockIdx.y * 64, ACT);
}

// ---------------- merged pre-phase: fc1(1200) | proj(600) | zero(400) | w2frag(192) ----------------
__global__ void __launch_bounds__(128) pre_all(
    const float* __restrict__ hidden, const float* __restrict__ fc1w, const float* __restrict__ fc1b,
    const float* __restrict__ inputs,
    const float* __restrict__ ir_w, const float* __restrict__ ii_w, const float* __restrict__ in_w,
    const float* __restrict__ ir_b, const float* __restrict__ ii_b, const float* __restrict__ in_b,
    const float* __restrict__ fc2w)
{
    int bid = blockIdx.x;
    int t = threadIdx.x;
    if (bid < 1200) {
        int z = bid / 200, rem = bid - z * 200;
        int bm = (rem % 50) * 64, bn = (rem / 50) * 64;
        int kk = z >> 1, half = z & 1, kt = kk + 1;
        const float* Bw = fc1w + (size_t)kt * 256 * 512 + half * 256;
        const float* bias = half ? nullptr : fc1b + kt * 256;
        float* C = g_scratch + (half ? HS_OFF : HR_OFF) + (size_t)kk * 819200;
        gemm_core(hidden, NHID, Bw, 512, bias, C, NHID, NHID, bm, bn, 0);
    } else if (bid < 1800) {
        int b2 = bid - 1200;
        int z = b2 / 200, rem = b2 - z * 200;
        int bm = (rem % 50) * 64, bn = (rem / 50) * 64;
        const float* w = (z == 0) ? ir_w : (z == 1) ? ii_w : in_w;
        const float* b = (z == 0) ? ir_b : (z == 1) ? ii_b : in_b;
        float* C = g_scratch + ((z == 0) ? TR_OFF : (z == 1) ? TI_OFF : TN_OFF);
        gemm_core(inputs, NIN, w, NIN, b, C, NHID, NIN, bm, bn, 0);
    } else if (bid < 2200) {
        int b2 = bid - 1800;
        float4* p = (float4*)(g_scratch + AGG_OFF) + (size_t)b2 * 512 + t * 4;
        float4 z4 = make_float4(0.f, 0.f, 0.f, 0.f);
#pragma unroll
        for (int j = 0; j < 4; ++j) p[j] = z4;
    } else {
        int b2 = bid - 2200;
        int p0 = (b2 * 128 + t) * 4;
#pragma unroll
        for (int j = 0; j < 4; ++j) {
            int p = p0 + j;
            int lane = p & 31;
            int reg = (p >> 5) & 1;
            int tile = (p >> 6) & 63;
            int kstep = tile & 1, ntile = tile >> 1;
            int c = (p >> 12) & 7;
            int kk = p >> 15;
            int n = ntile * 8 + (lane >> 2);
            int k = c * 32 + kstep * 16 + reg * 8 + (lane & 3) * 2;
            const float* w = fc2w + (size_t)(kk + 1) * 65536 + (size_t)n * 256 + k;
            g_wf[p] = pack_bf16(w[0], w[1]);
        }
    }
}

// ---------------- bf16 mma.sync edge kernel (full N=256 per block) ----------------
// grid (25, 50, 3): x = m-tile (128 rows g = b*50+i), y = receiver r, z = kk (kt=kk+1).
// 512 threads = 16 warps (4M x 4N); warp tile M32 x N64 (mt 2 x nt 8), m16n8k16 bf16.
// X generated once per (m-tile, r, kk); W streamed pre-packed from g_wf.
// Dynamic smem: As[2][2048] | Bs[2][4096] | bias[256]  (49 KB)
__global__ void __launch_bounds__(512, 1) edge_mma(
    const float* __restrict__ edges,
    const float* __restrict__ fc2b)
{
    extern __shared__ uint32_t dsm[];
    uint32_t* As_w0 = dsm;                      // [2][2048]
    uint32_t* Bs_w0 = dsm + EDGE_AS_WORDS;      // [2][4096]
    float* biasS = (float*)(dsm + EDGE_AS_WORDS + EDGE_BS_WORDS);

    int t = threadIdx.x;
    int wid = t >> 5, lid = t & 31;
    int m0 = blockIdx.x * 128;
    int r = blockIdx.y;
    int kk = blockIdx.z, kt = kk + 1;

    const float* HR = g_scratch + HR_OFF + (size_t)kk * 819200;
    const float* HS = g_scratch + HS_OFF + (size_t)kk * 819200;

    if (t < 256) biasS[t] = fc2b[kt * 256 + t];

    // generator indexing
    int grow = t >> 2;           // 0..127
    int kq = t & 3;
    int kstep = kq >> 1, khalf = kq & 1;
    int gg = m0 + grow;
    int gb = gg / 50, gi = gg - gb * 50;
    uint32_t hr_base = (uint32_t)(gb * 50 + r) * 256 + kq * 8;
    uint32_t hs_base = (uint32_t)(gb * 50 + gi) * 256 + kq * 8;
    int mtile = grow >> 4, rl = grow & 15;
    uint32_t a_sts = (uint32_t)(((mtile * 2 + kstep) * 4) + (rl >> 3) + 2 * khalf) * 32
                     + (rl & 7) * 4;
    const uint32_t* wf = g_wf + (size_t)kk * 32768 + t * 8;

    int mw = wid >> 2, nw = wid & 3;   // 4 m-warps x 4 n-warps

    float acc[2][8][4];
#pragma unroll
    for (int mt = 0; mt < 2; ++mt)
#pragma unroll
        for (int nt = 0; nt < 8; ++nt)
#pragma unroll
            for (int q = 0; q < 4; ++q) acc[mt][nt][q] = 0.0f;

    float4 hr0, hr1, hs0, hs1;
    uint4 wv0, wv1;

#define LDG_CHUNK(c) do { \
        const float* hp = HR + hr_base + (c) * 32; \
        const float* sp = HS + hs_base + (c) * 32; \
        hr0 = *(const float4*)hp; hr1 = *(const float4*)(hp + 4); \
        hs0 = *(const float4*)sp; hs1 = *(const float4*)(sp + 4); \
        wv0 = *(const uint4*)(wf + (c) * 4096); \
        wv1 = *(const uint4*)(wf + (c) * 4096 + 4); \
    } while (0)

#define STS_CHUNK(st) do { \
        uint4 xa; \
        xa.x = pack_bf16(tanha(hr0.x + hs0.x), tanha(hr0.y + hs0.y)); \
        xa.y = pack_bf16(tanha(hr0.z + hs0.z), tanha(hr0.w + hs0.w)); \
        xa.z = pack_bf16(tanha(hr1.x + hs1.x), tanha(hr1.y + hs1.y)); \
        xa.w = pack_bf16(tanha(hr1.z + hs1.z), tanha(hr1.w + hs1.w)); \
        *(uint4*)&As_w0[(st) * 2048 + a_sts] = xa; \
        *(uint4*)&Bs_w0[(st) * 4096 + t * 8] = wv0; \
        *(uint4*)&Bs_w0[(st) * 4096 + t * 8 + 4] = wv1; \
    } while (0)

    LDG_CHUNK(0);
    STS_CHUNK(0);
    LDG_CHUNK(1);

    for (int c = 0; c < 8; ++c) {
        int st = c & 1;
        __syncthreads();
        const uint32_t* Asb = As_w0 + st * 2048;
        const uint32_t* Bsb = Bs_w0 + st * 4096;
#pragma unroll
        for (int ks = 0; ks < 2; ++ks) {
            uint32_t a[2][4];
#pragma unroll
            for (int mt = 0; mt < 2; ++mt) {
                int tile = (mw * 2 + mt) * 2 + ks;
#pragma unroll
                for (int rg = 0; rg < 4; ++rg)
                    a[mt][rg] = Asb[(tile * 4 + rg) * 32 + lid];
            }
#pragma unroll
            for (int nt = 0; nt < 8; ++nt) {
                int tile = (nw * 8 + nt) * 2 + ks;
                uint32_t b0 = Bsb[(tile * 2 + 0) * 32 + lid];
                uint32_t b1 = Bsb[(tile * 2 + 1) * 32 + lid];
                mma_bf16(acc[0][nt], a[0], b0, b1);
                mma_bf16(acc[1][nt], a[1], b0, b1);
            }
        }
        if (c < 7) {
            STS_CHUNK((c + 1) & 1);
            if (c < 6) LDG_CHUNK(c + 2);
        }
    }

    // epilogue
    int lq = lid & 3, lr = lid >> 2;
    int base_row = mw * 32;
    int bfirst = (m0 + base_row) / 50;
    int blast = (m0 + base_row + 31) / 50;
    int has1 = (blast != bfirst);

    float wgt[4];
    int sg[4];
#pragma unroll
    for (int j = 0; j < 4; ++j) {
        int mt = j >> 1, rh = j & 1;
        int row_local = base_row + mt * 16 + rh * 8 + lr;
        int g = m0 + row_local;
        int b = g / 50, i = g - b * 50;
        sg[j] = b - bfirst;
        float w = 0.0f;
        if (i != r) {
            int e = i * 49 + r - (i < r ? 1 : 0);
            w = __ldg(&edges[((size_t)b * NEDGE + e) * 4 + kt]) * (1.0f / 147.0f);
        }
        wgt[j] = w;
    }

    float* agg0 = g_scratch + AGG_OFF + ((size_t)(bfirst * 50 + r)) * 256;

#pragma unroll
    for (int nt = 0; nt < 8; ++nt) {
        int colg = nw * 64 + nt * 8 + lq * 2;
        float b0 = biasS[colg], b1 = biasS[colg + 1];
        float c0[2] = {0.0f, 0.0f}, c1[2] = {0.0f, 0.0f};
#pragma unroll
        for (int j = 0; j < 4; ++j) {
            int mt = j >> 1, rh = j & 1;
            float t0 = tanha(acc[mt][nt][rh * 2 + 0] + b0) * wgt[j];
            float t1 = tanha(acc[mt][nt][rh * 2 + 1] + b1) * wgt[j];
            if (sg[j] == 0) { c0[0] += t0; c1[0] += t1; }
            else            { c0[1] += t0; c1[1] += t1; }
        }
#pragma unroll
        for (int o = 4; o <= 16; o <<= 1) {
            c0[0] += __shfl_xor_sync(0xffffffffu, c0[0], o);
            c1[0] += __shfl_xor_sync(0xffffffffu, c1[0], o);
            if (has1) {
                c0[1] += __shfl_xor_sync(0xffffffffu, c0[1], o);
                c1[1] += __shfl_xor_sync(0xffffffffu, c1[1], o);
            }
        }
        if (lid < 4) {
            atomicAdd(&agg0[colg], c0[0]);
            atomicAdd(&agg0[colg + 1], c1[0]);
            if (has1) {
                atomicAdd(&agg0[12800 + colg], c0[1]);
                atomicAdd(&agg0[12800 + colg + 1], c1[1]);
            }
        }
    }
#undef LDG_CHUNK
#undef STS_CHUNK
}

// ---------------- fused gate GEMMs + GRU combine ----------------
// grid (50, 4), 256 threads (16x16), BM=64, BN=64, thread tile 4x4.
__global__ void __launch_bounds__(256) gate_gru(
    const float* __restrict__ hr_w, const float* __restrict__ hi_w, const float* __restrict__ hh_w,
    const float* __restrict__ hidden, float* __restrict__ new_hidden)
{
    __shared__ float As[16][65];
    __shared__ float Br[16][68], Bi[16][68], Bh[16][68];

    int t = threadIdx.x;
    int bm = blockIdx.x * 64, bn = blockIdx.y * 64;
    int ty = t >> 4, tx = t & 15;
    const float* A = g_scratch + AGG_OFF;

    float ar[4][4], ai[4][4], ah[4][4];
#pragma unroll
    for (int m = 0; m < 4; ++m)
#pragma unroll
        for (int n = 0; n < 4; ++n) { ar[m][n] = 0.f; ai[m][n] = 0.f; ah[m][n] = 0.f; }

    for (int kb = 0; kb < 256; kb += 16) {
        __syncthreads();
        {
            int row = t >> 2, c = t & 3;
            float4 av = *(const float4*)&A[(size_t)(bm + row) * 256 + kb + c * 4];
            As[c * 4 + 0][row] = av.x; As[c * 4 + 1][row] = av.y;
            As[c * 4 + 2][row] = av.z; As[c * 4 + 3][row] = av.w;
            float4 rv = *(const float4*)&hr_w[(size_t)(bn + row) * 256 + kb + c * 4];
            Br[c * 4 + 0][row] = rv.x; Br[c * 4 + 1][row] = rv.y;
            Br[c * 4 + 2][row] = rv.z; Br[c * 4 + 3][row] = rv.w;
            float4 iv = *(const float4*)&hi_w[(size_t)(bn + row) * 256 + kb + c * 4];
            Bi[c * 4 + 0][row] = iv.x; Bi[c * 4 + 1][row] = iv.y;
            Bi[c * 4 + 2][row] = iv.z; Bi[c * 4 + 3][row] = iv.w;
            float4 hv = *(const float4*)&hh_w[(size_t)(bn + row) * 256 + kb + c * 4];
            Bh[c * 4 + 0][row] = hv.x; Bh[c * 4 + 1][row] = hv.y;
            Bh[c * 4 + 2][row] = hv.z; Bh[c * 4 + 3][row] = hv.w;
        }
        __syncthreads();
#pragma unroll
        for (int k2 = 0; k2 < 16; ++k2) {
            float a[4];
#pragma unroll
            for (int m = 0; m < 4; ++m) a[m] = As[k2][ty * 4 + m];
#pragma unroll
            for (int n = 0; n < 4; ++n) {
                float br = Br[k2][tx * 4 + n];
                float bi = Bi[k2][tx * 4 + n];
                float bh = Bh[k2][tx * 4 + n];
#pragma unroll
                for (int m = 0; m < 4; ++m) {
                    ar[m][n] += a[m] * br;
                    ai[m][n] += a[m] * bi;
                    ah[m][n] += a[m] * bh;
                }
            }
        }
    }

    const float* tr = g_scratch + TR_OFF;
    const float* ti = g_scratch + TI_OFF;
    const float* tn = g_scratch + TN_OFF;
#pragma unroll
    for (int m = 0; m < 4; ++m) {
        int row = bm + ty * 4 + m;
#pragma unroll
        for (int n = 0; n < 4; ++n) {
            int col = bn + tx * 4 + n;
            size_t idx = (size_t)row * 256 + col;
            float r_ = sigm(ar[m][n] + tr[idx]);
            float i_ = sigm(ai[m][n] + ti[idx]);
            float n_ = tanha(tn[idx] + r_ * ah[m][n]);
            new_hidden[idx] = (1.0f - i_) * n_ + i_ * hidden[idx];
        }
    }
}

// ---------------- launch ----------------
extern "C" void kernel_launch(void* const* d_in, const int* in_sizes, int n_in,
                              void* d_out, int out_size) {
    const float* inputs = (const float*)d_in[0];
    const float* hidden = (const float*)d_in[1];
    const float* edges  = (const float*)d_in[2];
    const float* fc1w   = (const float*)d_in[3];
    const float* fc1b   = (const float*)d_in[4];
    const float* fc2w   = (const float*)d_in[5];
    const float* fc2b   = (const float*)d_in[6];
    const float* hr_w   = (const float*)d_in[7];
    const float* hi_w   = (const float*)d_in[8];
    const float* hh_w   = (const float*)d_in[9];
    const float* ir_w   = (const float*)d_in[10];
    const float* ir_b   = (const float*)d_in[11];
    const float* ii_w   = (const float*)d_in[12];
    const float* ii_b   = (const float*)d_in[13];
    const float* in_w   = (const float*)d_in[14];
    const float* in_b   = (const float*)d_in[15];
    const float* of1_w  = (const float*)d_in[16];
    const float* of1_b  = (const float*)d_in[17];
    const float* of2_w  = (const float*)d_in[18];
    const float* of2_b  = (const float*)d_in[19];
    const float* mu_w   = (const float*)d_in[20];
    const float* mu_b   = (const float*)d_in[21];

    float* out = (float*)d_out;
    float* out_mu   = out;               // [64,50,64]
    float* out_nh   = out + 204800;      // [64,50,256]
    float* out_pred = out + 1024000;     // [64,50,256]

    float* S = nullptr;
    cudaGetSymbolAddress((void**)&S, g_scratch);

    cudaFuncSetAttribute(edge_mma, cudaFuncAttributeMaxDynamicSharedMemorySize, EDGE_SMEM_BYTES);

    const int M = BATCH * NVARS;  // 3200

    pre_all<<<2392, 128>>>(hidden, fc1w, fc1b, inputs,
                           ir_w, ii_w, in_w, ir_b, ii_b, in_b, fc2w);

    edge_mma<<<dim3(25, NVARS, 3), 512, EDGE_SMEM_BYTES>>>(edges, fc2b);

    gate_gru<<<dim3(50, 4), 256>>>(hr_w, hi_w, hh_w, hidden, out_nh);

    gemm_nt<3><<<dim3(M / 64, 4), 128>>>(out_nh, NHID, of1_w, NHID, of1_b, S + P1_OFF, NHID, NHID);
    gemm_nt<3><<<dim3(M / 64, 4), 128>>>(S + P1_OFF, NHID, of2_w, NHID, of2_b, out_pred, NHID, NHID);
    gemm_nt<0><<<dim3(M / 64, 1), 128>>>(out_pred, NHID, mu_w, NHID, mu_b, out_mu, NIN, NHID);
}

// round 9
// speedup vs baseline: 3.9676x; 1.1362x over previous
#include <cuda_runtime.h>
#include <cstdint>
#include <cstddef>

// ---------------- constants ----------------
#define BATCH 64
#define NVARS 50
#define NHID 256
#define NIN 64
#define NEDGE 2450

// scratch layout (floats)
#define AGG_OFF  ((size_t)0)          // 3200*256
#define TR_OFF   ((size_t)819200)
#define TI_OFF   ((size_t)1638400)
#define TN_OFF   ((size_t)2457600)
#define P1_OFF   ((size_t)3276800)
#define SCRATCH_TOTAL ((size_t)4096000)

__device__ float g_scratch[SCRATCH_TOTAL];
// fc2 W fragments, bf16x2 words: [kk(3)][chunk(8)][4096 words]
#define WF_WORDS (3 * 8 * 4096)
__device__ uint32_t g_wf[WF_WORDS];
// Hr/Hs bf16x2 words: [kk(3)][half(2)][row(3200)][128 words]
#define HH_ROW_WORDS 128
#define HH_PLANE ((size_t)3200 * 128)   // 409600
__device__ uint32_t g_hrhs[6 * 409600];

// dynamic smem (uint32 words): As[2][2048] | Bs[2][4096] | bias[256]
#define EDGE_AS_WORDS   (2 * 2048)
#define EDGE_BS_WORDS   (2 * 4096)
#define EDGE_SMEM_BYTES ((EDGE_AS_WORDS + EDGE_BS_WORDS + 256) * 4)

static __device__ __forceinline__ float tanha(float x) {
    float y; asm("tanh.approx.f32 %0, %1;" : "=f"(y) : "f"(x)); return y;
}
static __device__ __forceinline__ float sigm(float x) {
    return 1.0f / (1.0f + __expf(-x));
}
static __device__ __forceinline__ uint32_t pack_bf16(float lo, float hi) {
    uint32_t d; asm("cvt.rn.bf16x2.f32 %0, %1, %2;" : "=r"(d) : "f"(hi), "f"(lo));
    return d;
}
static __device__ __forceinline__ uint32_t add_bf16x2(uint32_t a, uint32_t b) {
    uint32_t d; asm("add.rn.bf16x2 %0, %1, %2;" : "=r"(d) : "r"(a), "r"(b));
    return d;
}
static __device__ __forceinline__ uint32_t tanh_bf16x2(uint32_t x) {
    uint32_t y; asm("tanh.approx.bf16x2 %0, %1;" : "=r"(y) : "r"(x));
    return y;
}

// m16n8k16 bf16 mma
static __device__ __forceinline__ void mma_bf16(float* d, const uint32_t* a,
                                                uint32_t b0, uint32_t b1) {
    asm volatile(
        "mma.sync.aligned.m16n8k16.row.col.f32.bf16.bf16.f32 "
        "{%0,%1,%2,%3}, {%4,%5,%6,%7}, {%8,%9}, {%0,%1,%2,%3};"
        : "+f"(d[0]), "+f"(d[1]), "+f"(d[2]), "+f"(d[3])
        : "r"(a[0]), "r"(a[1]), "r"(a[2]), "r"(a[3]), "r"(b0), "r"(b1));
}

// ---------------- generic NT GEMM core (fp32 tail) ----------------
static __device__ __forceinline__ void gemm_core(
    const float* __restrict__ A, int lda,
    const float* __restrict__ Bw, int ldb,
    const float* __restrict__ bias,
    float* __restrict__ C,
    int N, int K, int bm, int bn, int act)
{
    __shared__ float As[16][65];
    __shared__ float Bs[16][68];

    int t = threadIdx.x;
    int ty = t >> 4;
    int tx = t & 15;

    float acc[8][4];
#pragma unroll
    for (int m = 0; m < 8; ++m)
#pragma unroll
        for (int n = 0; n < 4; ++n) acc[m][n] = 0.0f;

    for (int kb = 0; kb < K; kb += 16) {
        __syncthreads();
#pragma unroll
        for (int j = 0; j < 2; ++j) {
            int f4 = t * 2 + j;
            int row = f4 >> 2;
            int c = f4 & 3;
            float4 av = *(const float4*)&A[(size_t)(bm + row) * lda + kb + c * 4];
            As[c * 4 + 0][row] = av.x; As[c * 4 + 1][row] = av.y;
            As[c * 4 + 2][row] = av.z; As[c * 4 + 3][row] = av.w;
            float4 bv = *(const float4*)&Bw[(size_t)(bn + row) * ldb + kb + c * 4];
            Bs[c * 4 + 0][row] = bv.x; Bs[c * 4 + 1][row] = bv.y;
            Bs[c * 4 + 2][row] = bv.z; Bs[c * 4 + 3][row] = bv.w;
        }
        __syncthreads();
#pragma unroll
        for (int k2 = 0; k2 < 16; ++k2) {
            float a[8];
#pragma unroll
            for (int m = 0; m < 8; ++m) a[m] = As[k2][ty * 8 + m];
            float4 bv = *(const float4*)&Bs[k2][tx * 4];
            float b4[4] = {bv.x, bv.y, bv.z, bv.w};
#pragma unroll
            for (int m = 0; m < 8; ++m)
#pragma unroll
                for (int n = 0; n < 4; ++n) acc[m][n] += a[m] * b4[n];
        }
    }

#pragma unroll
    for (int m = 0; m < 8; ++m) {
        int row = bm + ty * 8 + m;
#pragma unroll
        for (int n = 0; n < 4; ++n) {
            int col = bn + tx * 4 + n;
            float v = acc[m][n];
            if (bias) v += bias[col];
            if (act == 3) v = fmaxf(v, 0.0f);
            C[(size_t)row * N + col] = v;
        }
    }
}

template <int ACT>
__global__ void __launch_bounds__(128) gemm_nt(
    const float* __restrict__ A, int lda,
    const float* __restrict__ Bw, int ldb,
    const float* __restrict__ bias,
    float* __restrict__ C, int N, int K)
{
    gemm_core(A, lda, Bw, ldb, bias, C, N, K, blockIdx.x * 64, blockIdx.y * 64, ACT);
}

// ---------------- pre-phase: proj(600) | zero(400) | fc2 w2frag(192) ----------------
__global__ void __launch_bounds__(128) pre_all(
    const float* __restrict__ inputs,
    const float* __restrict__ ir_w, const float* __restrict__ ii_w, const float* __restrict__ in_w,
    const float* __restrict__ ir_b, const float* __restrict__ ii_b, const float* __restrict__ in_b,
    const float* __restrict__ fc2w)
{
    int bid = blockIdx.x;
    int t = threadIdx.x;
    if (bid < 600) {
        int z = bid / 200, rem = bid - z * 200;
        int bm = (rem % 50) * 64, bn = (rem / 50) * 64;
        const float* w = (z == 0) ? ir_w : (z == 1) ? ii_w : in_w;
        const float* b = (z == 0) ? ir_b : (z == 1) ? ii_b : in_b;
        float* C = g_scratch + ((z == 0) ? TR_OFF : (z == 1) ? TI_OFF : TN_OFF);
        gemm_core(inputs, NIN, w, NIN, b, C, NHID, NIN, bm, bn, 0);
    } else if (bid < 1000) {
        int b2 = bid - 600;
        float4* p = (float4*)(g_scratch + AGG_OFF) + (size_t)b2 * 512 + t * 4;
        float4 z4 = make_float4(0.f, 0.f, 0.f, 0.f);
#pragma unroll
        for (int j = 0; j < 4; ++j) p[j] = z4;
    } else {
        int b2 = bid - 1000;
        int p0 = (b2 * 128 + t) * 4;
#pragma unroll
        for (int j = 0; j < 4; ++j) {
            int p = p0 + j;
            int lane = p & 31;
            int reg = (p >> 5) & 1;
            int tile = (p >> 6) & 63;
            int kstep = tile & 1, ntile = tile >> 1;
            int c = (p >> 12) & 7;
            int kk = p >> 15;
            int n = ntile * 8 + (lane >> 2);
            int k = c * 32 + kstep * 16 + reg * 8 + (lane & 3) * 2;
            const float* w = fc2w + (size_t)(kk + 1) * 65536 + (size_t)n * 256 + k;
            g_wf[p] = pack_bf16(w[0], w[1]);
        }
    }
}

// ---------------- fc1 via bf16 mma: Hr/Hs -> g_hrhs (bf16) ----------------
// grid (25, 3, 2): m-tile, kk, half (0 = Hr [+bias], 1 = Hs).
// Block 128 rows x 256 cols, K = 256. Same fragment machinery as edge_mma;
// A = hidden (fp32 -> bf16), B = fc1w slice (fp32 -> bf16).
__global__ void __launch_bounds__(512, 1) fc1_mma(
    const float* __restrict__ hidden,
    const float* __restrict__ fc1w,
    const float* __restrict__ fc1b)
{
    extern __shared__ uint32_t dsm[];
    uint32_t* As_w0 = dsm;
    uint32_t* Bs_w0 = dsm + EDGE_AS_WORDS;
    float* biasS = (float*)(dsm + EDGE_AS_WORDS + EDGE_BS_WORDS);

    int t = threadIdx.x;
    int wid = t >> 5, lid = t & 31;
    int m0 = blockIdx.x * 128;
    int kk = blockIdx.y, half = blockIdx.z, kt = kk + 1;

    if (t < 256) biasS[t] = half ? 0.0f : fc1b[kt * 256 + t];

    // A generator (identical mapping to edge_mma)
    int grow = t >> 2, kq = t & 3;
    int kstep = kq >> 1, khalf = kq & 1;
    int mtile = grow >> 4, rl = grow & 15;
    uint32_t a_sts = (uint32_t)(((mtile * 2 + kstep) * 4) + (rl >> 3) + 2 * khalf) * 32
                     + (rl & 7) * 4;
    const float* Abase = hidden + (size_t)(m0 + grow) * 256 + kq * 8;

    // B generator (inverse of w2frag mapping)
    int nn = t >> 1, kh = t & 1;
    const float* Bbase = fc1w + (size_t)kt * 131072 + (size_t)nn * 512 + half * 256 + kh * 16;
    int btile = (nn >> 3) * 2 + kh;
    uint32_t b_sts0 = (uint32_t)(btile * 2 + 0) * 32 + (nn & 7) * 4;
    uint32_t b_sts1 = (uint32_t)(btile * 2 + 1) * 32 + (nn & 7) * 4;

    int mw = wid >> 2, nw = wid & 3;

    float acc[2][8][4];
#pragma unroll
    for (int mt = 0; mt < 2; ++mt)
#pragma unroll
        for (int nt = 0; nt < 8; ++nt)
#pragma unroll
            for (int q = 0; q < 4; ++q) acc[mt][nt][q] = 0.0f;

    float4 av0, av1, bv0, bv1, bv2, bv3;

#define F1_LDG(c) do { \
        av0 = *(const float4*)(Abase + (c) * 32); \
        av1 = *(const float4*)(Abase + (c) * 32 + 4); \
        bv0 = *(const float4*)(Bbase + (c) * 32); \
        bv1 = *(const float4*)(Bbase + (c) * 32 + 4); \
        bv2 = *(const float4*)(Bbase + (c) * 32 + 8); \
        bv3 = *(const float4*)(Bbase + (c) * 32 + 12); \
    } while (0)

#define F1_STS(st) do { \
        uint4 xa; \
        xa.x = pack_bf16(av0.x, av0.y); xa.y = pack_bf16(av0.z, av0.w); \
        xa.z = pack_bf16(av1.x, av1.y); xa.w = pack_bf16(av1.z, av1.w); \
        *(uint4*)&As_w0[(st) * 2048 + a_sts] = xa; \
        uint4 w0, w1; \
        w0.x = pack_bf16(bv0.x, bv0.y); w0.y = pack_bf16(bv0.z, bv0.w); \
        w0.z = pack_bf16(bv1.x, bv1.y); w0.w = pack_bf16(bv1.z, bv1.w); \
        w1.x = pack_bf16(bv2.x, bv2.y); w1.y = pack_bf16(bv2.z, bv2.w); \
        w1.z = pack_bf16(bv3.x, bv3.y); w1.w = pack_bf16(bv3.z, bv3.w); \
        *(uint4*)&Bs_w0[(st) * 4096 + b_sts0] = w0; \
        *(uint4*)&Bs_w0[(st) * 4096 + b_sts1] = w1; \
    } while (0)

    F1_LDG(0);
    F1_STS(0);
    F1_LDG(1);

    for (int c = 0; c < 8; ++c) {
        int st = c & 1;
        __syncthreads();
        const uint32_t* Asb = As_w0 + st * 2048;
        const uint32_t* Bsb = Bs_w0 + st * 4096;
#pragma unroll
        for (int ks = 0; ks < 2; ++ks) {
            uint32_t a[2][4];
#pragma unroll
            for (int mt = 0; mt < 2; ++mt) {
                int tile = (mw * 2 + mt) * 2 + ks;
#pragma unroll
                for (int rg = 0; rg < 4; ++rg)
                    a[mt][rg] = Asb[(tile * 4 + rg) * 32 + lid];
            }
#pragma unroll
            for (int nt = 0; nt < 8; ++nt) {
                int tile = (nw * 8 + nt) * 2 + ks;
                uint32_t b0 = Bsb[(tile * 2 + 0) * 32 + lid];
                uint32_t b1 = Bsb[(tile * 2 + 1) * 32 + lid];
                mma_bf16(acc[0][nt], a[0], b0, b1);
                mma_bf16(acc[1][nt], a[1], b0, b1);
            }
        }
        if (c < 7) {
            F1_STS((c + 1) & 1);
            if (c < 6) F1_LDG(c + 2);
        }
    }

    // epilogue: bias + pack bf16 pairs, row-major words
    int lq = lid & 3, lr = lid >> 2;
    uint32_t* outp = g_hrhs + (size_t)(kk * 2 + half) * HH_PLANE;
#pragma unroll
    for (int mt = 0; mt < 2; ++mt)
#pragma unroll
        for (int rh = 0; rh < 2; ++rh) {
            int row = m0 + mw * 32 + mt * 16 + rh * 8 + lr;
#pragma unroll
            for (int nt = 0; nt < 8; ++nt) {
                int col = nw * 64 + nt * 8 + lq * 2;
                float v0 = acc[mt][nt][rh * 2 + 0] + biasS[col];
                float v1 = acc[mt][nt][rh * 2 + 1] + biasS[col + 1];
                outp[(size_t)row * HH_ROW_WORDS + (col >> 1)] = pack_bf16(v0, v1);
            }
        }
#undef F1_LDG
#undef F1_STS
}

// ---------------- bf16 mma.sync edge kernel ----------------
// grid (25, 50, 3). HR/HS read as bf16 words; X = tanh_bf16x2(hr + hs).
__global__ void __launch_bounds__(512, 1) edge_mma(
    const float* __restrict__ edges,
    const float* __restrict__ fc2b)
{
    extern __shared__ uint32_t dsm[];
    uint32_t* As_w0 = dsm;
    uint32_t* Bs_w0 = dsm + EDGE_AS_WORDS;
    float* biasS = (float*)(dsm + EDGE_AS_WORDS + EDGE_BS_WORDS);

    int t = threadIdx.x;
    int wid = t >> 5, lid = t & 31;
    int m0 = blockIdx.x * 128;
    int r = blockIdx.y;
    int kk = blockIdx.z, kt = kk + 1;

    const uint32_t* HRw = g_hrhs + (size_t)(kk * 2 + 0) * HH_PLANE;
    const uint32_t* HSw = g_hrhs + (size_t)(kk * 2 + 1) * HH_PLANE;

    if (t < 256) biasS[t] = fc2b[kt * 256 + t];

    // generator indexing
    int grow = t >> 2, kq = t & 3;
    int kstep = kq >> 1, khalf = kq & 1;
    int gg = m0 + grow;
    int gb = gg / 50, gi = gg - gb * 50;
    uint32_t hr_base = (uint32_t)(gb * 50 + r) * HH_ROW_WORDS + kq * 4;
    uint32_t hs_base = (uint32_t)(gb * 50 + gi) * HH_ROW_WORDS + kq * 4;
    int mtile = grow >> 4, rl = grow & 15;
    uint32_t a_sts = (uint32_t)(((mtile * 2 + kstep) * 4) + (rl >> 3) + 2 * khalf) * 32
                     + (rl & 7) * 4;
    const uint32_t* wf = g_wf + (size_t)kk * 32768 + t * 8;

    int mw = wid >> 2, nw = wid & 3;

    float acc[2][8][4];
#pragma unroll
    for (int mt = 0; mt < 2; ++mt)
#pragma unroll
        for (int nt = 0; nt < 8; ++nt)
#pragma unroll
            for (int q = 0; q < 4; ++q) acc[mt][nt][q] = 0.0f;

    uint4 hv, sv, wv0, wv1;

#define LDG_CHUNK(c) do { \
        hv = *(const uint4*)(HRw + hr_base + (c) * 16); \
        sv = *(const uint4*)(HSw + hs_base + (c) * 16); \
        wv0 = *(const uint4*)(wf + (c) * 4096); \
        wv1 = *(const uint4*)(wf + (c) * 4096 + 4); \
    } while (0)

#define STS_CHUNK(st) do { \
        uint4 xa; \
        xa.x = tanh_bf16x2(add_bf16x2(hv.x, sv.x)); \
        xa.y = tanh_bf16x2(add_bf16x2(hv.y, sv.y)); \
        xa.z = tanh_bf16x2(add_bf16x2(hv.z, sv.z)); \
        xa.w = tanh_bf16x2(add_bf16x2(hv.w, sv.w)); \
        *(uint4*)&As_w0[(st) * 2048 + a_sts] = xa; \
        *(uint4*)&Bs_w0[(st) * 4096 + t * 8] = wv0; \
        *(uint4*)&Bs_w0[(st) * 4096 + t * 8 + 4] = wv1; \
    } while (0)

    LDG_CHUNK(0);
    STS_CHUNK(0);
    LDG_CHUNK(1);

    for (int c = 0; c < 8; ++c) {
        int st = c & 1;
        __syncthreads();
        const uint32_t* Asb = As_w0 + st * 2048;
        const uint32_t* Bsb = Bs_w0 + st * 4096;
#pragma unroll
        for (int ks = 0; ks < 2; ++ks) {
            uint32_t a[2][4];
#pragma unroll
            for (int mt = 0; mt < 2; ++mt) {
                int tile = (mw * 2 + mt) * 2 + ks;
#pragma unroll
                for (int rg = 0; rg < 4; ++rg)
                    a[mt][rg] = Asb[(tile * 4 + rg) * 32 + lid];
            }
#pragma unroll
            for (int nt = 0; nt < 8; ++nt) {
                int tile = (nw * 8 + nt) * 2 + ks;
                uint32_t b0 = Bsb[(tile * 2 + 0) * 32 + lid];
                uint32_t b1 = Bsb[(tile * 2 + 1) * 32 + lid];
                mma_bf16(acc[0][nt], a[0], b0, b1);
                mma_bf16(acc[1][nt], a[1], b0, b1);
            }
        }
        if (c < 7) {
            STS_CHUNK((c + 1) & 1);
            if (c < 6) LDG_CHUNK(c + 2);
        }
    }

    // epilogue
    int lq = lid & 3, lr = lid >> 2;
    int base_row = mw * 32;
    int bfirst = (m0 + base_row) / 50;
    int blast = (m0 + base_row + 31) / 50;
    int has1 = (blast != bfirst);

    float wgt[4];
    int sg[4];
#pragma unroll
    for (int j = 0; j < 4; ++j) {
        int mt = j >> 1, rh = j & 1;
        int row_local = base_row + mt * 16 + rh * 8 + lr;
        int g = m0 + row_local;
        int b = g / 50, i = g - b * 50;
        sg[j] = b - bfirst;
        float w = 0.0f;
        if (i != r) {
            int e = i * 49 + r - (i < r ? 1 : 0);
            w = __ldg(&edges[((size_t)b * NEDGE + e) * 4 + kt]) * (1.0f / 147.0f);
        }
        wgt[j] = w;
    }

    float* agg0 = g_scratch + AGG_OFF + ((size_t)(bfirst * 50 + r)) * 256;

#pragma unroll
    for (int nt = 0; nt < 8; ++nt) {
        int colg = nw * 64 + nt * 8 + lq * 2;
        float b0 = biasS[colg], b1 = biasS[colg + 1];
        float c0[2] = {0.0f, 0.0f}, c1[2] = {0.0f, 0.0f};
#pragma unroll
        for (int j = 0; j < 4; ++j) {
            int mt = j >> 1, rh = j & 1;
            float t0 = tanha(acc[mt][nt][rh * 2 + 0] + b0) * wgt[j];
            float t1 = tanha(acc[mt][nt][rh * 2 + 1] + b1) * wgt[j];
            if (sg[j] == 0) { c0[0] += t0; c1[0] += t1; }
            else            { c0[1] += t0; c1[1] += t1; }
        }
#pragma unroll
        for (int o = 4; o <= 16; o <<= 1) {
            c0[0] += __shfl_xor_sync(0xffffffffu, c0[0], o);
            c1[0] += __shfl_xor_sync(0xffffffffu, c1[0], o);
            if (has1) {
                c0[1] += __shfl_xor_sync(0xffffffffu, c0[1], o);
                c1[1] += __shfl_xor_sync(0xffffffffu, c1[1], o);
            }
        }
        if (lid < 4) {
            atomicAdd(&agg0[colg], c0[0]);
            atomicAdd(&agg0[colg + 1], c1[0]);
            if (has1) {
                atomicAdd(&agg0[12800 + colg], c0[1]);
                atomicAdd(&agg0[12800 + colg + 1], c1[1]);
            }
        }
    }
#undef LDG_CHUNK
#undef STS_CHUNK
}

// ---------------- fused gate GEMMs + GRU combine ----------------
__global__ void __launch_bounds__(256) gate_gru(
    const float* __restrict__ hr_w, const float* __restrict__ hi_w, const float* __restrict__ hh_w,
    const float* __restrict__ hidden, float* __restrict__ new_hidden)
{
    __shared__ float As[16][65];
    __shared__ float Br[16][68], Bi[16][68], Bh[16][68];

    int t = threadIdx.x;
    int bm = blockIdx.x * 64, bn = blockIdx.y * 64;
    int ty = t >> 4, tx = t & 15;
    const float* A = g_scratch + AGG_OFF;

    float ar[4][4], ai[4][4], ah[4][4];
#pragma unroll
    for (int m = 0; m < 4; ++m)
#pragma unroll
        for (int n = 0; n < 4; ++n) { ar[m][n] = 0.f; ai[m][n] = 0.f; ah[m][n] = 0.f; }

    for (int kb = 0; kb < 256; kb += 16) {
        __syncthreads();
        {
            int row = t >> 2, c = t & 3;
            float4 av = *(const float4*)&A[(size_t)(bm + row) * 256 + kb + c * 4];
            As[c * 4 + 0][row] = av.x; As[c * 4 + 1][row] = av.y;
            As[c * 4 + 2][row] = av.z; As[c * 4 + 3][row] = av.w;
            float4 rv = *(const float4*)&hr_w[(size_t)(bn + row) * 256 + kb + c * 4];
            Br[c * 4 + 0][row] = rv.x; Br[c * 4 + 1][row] = rv.y;
            Br[c * 4 + 2][row] = rv.z; Br[c * 4 + 3][row] = rv.w;
            float4 iv = *(const float4*)&hi_w[(size_t)(bn + row) * 256 + kb + c * 4];
            Bi[c * 4 + 0][row] = iv.x; Bi[c * 4 + 1][row] = iv.y;
            Bi[c * 4 + 2][row] = iv.z; Bi[c * 4 + 3][row] = iv.w;
            float4 hv = *(const float4*)&hh_w[(size_t)(bn + row) * 256 + kb + c * 4];
            Bh[c * 4 + 0][row] = hv.x; Bh[c * 4 + 1][row] = hv.y;
            Bh[c * 4 + 2][row] = hv.z; Bh[c * 4 + 3][row] = hv.w;
        }
        __syncthreads();
#pragma unroll
        for (int k2 = 0; k2 < 16; ++k2) {
            float a[4];
#pragma unroll
            for (int m = 0; m < 4; ++m) a[m] = As[k2][ty * 4 + m];
#pragma unroll
            for (int n = 0; n < 4; ++n) {
                float br = Br[k2][tx * 4 + n];
                float bi = Bi[k2][tx * 4 + n];
                float bh = Bh[k2][tx * 4 + n];
#pragma unroll
                for (int m = 0; m < 4; ++m) {
                    ar[m][n] += a[m] * br;
                    ai[m][n] += a[m] * bi;
                    ah[m][n] += a[m] * bh;
                }
            }
        }
    }

    const float* tr = g_scratch + TR_OFF;
    const float* ti = g_scratch + TI_OFF;
    const float* tn = g_scratch + TN_OFF;
#pragma unroll
    for (int m = 0; m < 4; ++m) {
        int row = bm + ty * 4 + m;
#pragma unroll
        for (int n = 0; n < 4; ++n) {
            int col = bn + tx * 4 + n;
            size_t idx = (size_t)row * 256 + col;
            float r_ = sigm(ar[m][n] + tr[idx]);
            float i_ = sigm(ai[m][n] + ti[idx]);
            float n_ = tanha(tn[idx] + r_ * ah[m][n]);
            new_hidden[idx] = (1.0f - i_) * n_ + i_ * hidden[idx];
        }
    }
}

// ---------------- launch ----------------
extern "C" void kernel_launch(void* const* d_in, const int* in_sizes, int n_in,
                              void* d_out, int out_size) {
    const float* inputs = (const float*)d_in[0];
    const float* hidden = (const float*)d_in[1];
    const float* edges  = (const float*)d_in[2];
    const float* fc1w   = (const float*)d_in[3];
    const float* fc1b   = (const float*)d_in[4];
    const float* fc2w   = (const float*)d_in[5];
    const float* fc2b   = (const float*)d_in[6];
    const float* hr_w   = (const float*)d_in[7];
    const float* hi_w   = (const float*)d_in[8];
    const float* hh_w   = (const float*)d_in[9];
    const float* ir_w   = (const float*)d_in[10];
    const float* ir_b   = (const float*)d_in[11];
    const float* ii_w   = (const float*)d_in[12];
    const float* ii_b   = (const float*)d_in[13];
    const float* in_w   = (const float*)d_in[14];
    const float* in_b   = (const float*)d_in[15];
    const float* of1_w  = (const float*)d_in[16];
    const float* of1_b  = (const float*)d_in[17];
    const float* of2_w  = (const float*)d_in[18];
    const float* of2_b  = (const float*)d_in[19];
    const float* mu_w   = (const float*)d_in[20];
    const float* mu_b   = (const float*)d_in[21];

    float* out = (float*)d_out;
    float* out_mu   = out;               // [64,50,64]
    float* out_nh   = out + 204800;      // [64,50,256]
    float* out_pred = out + 1024000;     // [64,50,256]

    float* S = nullptr;
    cudaGetSymbolAddress((void**)&S, g_scratch);

    cudaFuncSetAttribute(edge_mma, cudaFuncAttributeMaxDynamicSharedMemorySize, EDGE_SMEM_BYTES);
    cudaFuncSetAttribute(fc1_mma, cudaFuncAttributeMaxDynamicSharedMemorySize, EDGE_SMEM_BYTES);

    const int M = BATCH * NVARS;  // 3200

    fc1_mma<<<dim3(25, 3, 2), 512, EDGE_SMEM_BYTES>>>(hidden, fc1w, fc1b);
    pre_all<<<1192, 128>>>(inputs, ir_w, ii_w, in_w, ir_b, ii_b, in_b, fc2w);

    edge_mma<<<dim3(25, NVARS, 3), 512, EDGE_SMEM_BYTES>>>(edges, fc2b);

    gate_gru<<<dim3(50, 4), 256>>>(hr_w, hi_w, hh_w, hidden, out_nh);

    gemm_nt<3><<<dim3(M / 64, 4), 128>>>(out_nh, NHID, of1_w, NHID, of1_b, S + P1_OFF, NHID, NHID);
    gemm_nt<3><<<dim3(M / 64, 4), 128>>>(S + P1_OFF, NHID, of2_w, NHID, of2_b, out_pred, NHID, NHID);
    gemm_nt<0><<<dim3(M / 64, 1), 128>>>(out_pred, NHID, mu_w, NHID, mu_b, out_mu, NIN, NHID);
}

// round 10
// speedup vs baseline: 4.0813x; 1.0287x over previous
#include <cuda_runtime.h>
#include <cstdint>
#include <cstddef>

// ---------------- constants ----------------
#define BATCH 64
#define NVARS 50
#define NHID 256
#define NIN 64
#define NEDGE 2450

// scratch layout (floats)
#define AGG_OFF  ((size_t)0)          // 3200*256
#define TR_OFF   ((size_t)819200)
#define TI_OFF   ((size_t)1638400)
#define TN_OFF   ((size_t)2457600)
#define GR_OFF   ((size_t)3276800)
#define GI_OFF   ((size_t)4096000)
#define GH_OFF   ((size_t)4915200)
#define P1_OFF   ((size_t)5734400)
#define SCRATCH_TOTAL ((size_t)6553600)

__device__ float g_scratch[SCRATCH_TOTAL];
// fc2 W fragments, bf16x2 words: [kk(3)][chunk(8)][4096 words]
#define WF_WORDS (3 * 8 * 4096)
__device__ uint32_t g_wf[WF_WORDS];
// Hr/Hs bf16x2 words: [kk(3)][half(2)][row(3200)][128 words]
#define HH_ROW_WORDS 128
#define HH_PLANE ((size_t)3200 * 128)
__device__ uint32_t g_hrhs[6 * 409600];

// dynamic smem (uint32 words): As[2][2048] | Bs[2][4096] | bias[256]
#define EDGE_AS_WORDS   (2 * 2048)
#define EDGE_BS_WORDS   (2 * 4096)
#define EDGE_SMEM_BYTES ((EDGE_AS_WORDS + EDGE_BS_WORDS + 256) * 4)
// head smem: Ahi[2048] Alo[2048] Bhi[4096] Blo[4096] bias[256]
#define HEAD_SMEM_BYTES ((2048 + 2048 + 4096 + 4096 + 256) * 4)

static __device__ __forceinline__ float tanha(float x) {
    float y; asm("tanh.approx.f32 %0, %1;" : "=f"(y) : "f"(x)); return y;
}
static __device__ __forceinline__ float sigm(float x) {
    return 1.0f / (1.0f + __expf(-x));
}
static __device__ __forceinline__ uint32_t pack_bf16(float lo, float hi) {
    uint32_t d; asm("cvt.rn.bf16x2.f32 %0, %1, %2;" : "=r"(d) : "f"(hi), "f"(lo));
    return d;
}
static __device__ __forceinline__ uint32_t add_bf16x2(uint32_t a, uint32_t b) {
    uint32_t d; asm("add.rn.bf16x2 %0, %1, %2;" : "=r"(d) : "r"(a), "r"(b));
    return d;
}
static __device__ __forceinline__ uint32_t tanh_bf16x2(uint32_t x) {
    uint32_t y; asm("tanh.approx.bf16x2 %0, %1;" : "=r"(y) : "r"(x));
    return y;
}
// split fp32 pair into bf16 hi word + bf16 lo (residual) word
static __device__ __forceinline__ void split_bf16(float a, float b, uint32_t& hi, uint32_t& lo) {
    hi = pack_bf16(a, b);
    float ra = __uint_as_float(hi << 16);
    float rb = __uint_as_float(hi & 0xffff0000u);
    lo = pack_bf16(a - ra, b - rb);
}

// m16n8k16 bf16 mma
static __device__ __forceinline__ void mma_bf16(float* d, const uint32_t* a,
                                                uint32_t b0, uint32_t b1) {
    asm volatile(
        "mma.sync.aligned.m16n8k16.row.col.f32.bf16.bf16.f32 "
        "{%0,%1,%2,%3}, {%4,%5,%6,%7}, {%8,%9}, {%0,%1,%2,%3};"
        : "+f"(d[0]), "+f"(d[1]), "+f"(d[2]), "+f"(d[3])
        : "r"(a[0]), "r"(a[1]), "r"(a[2]), "r"(a[3]), "r"(b0), "r"(b1));
}

// ---------------- generic NT GEMM core (fp32, small cases) ----------------
static __device__ __forceinline__ void gemm_core(
    const float* __restrict__ A, int lda,
    const float* __restrict__ Bw, int ldb,
    const float* __restrict__ bias,
    float* __restrict__ C,
    int N, int K, int bm, int bn, int act)
{
    __shared__ float As[16][65];
    __shared__ float Bs[16][68];

    int t = threadIdx.x;
    int ty = t >> 4;
    int tx = t & 15;

    float acc[8][4];
#pragma unroll
    for (int m = 0; m < 8; ++m)
#pragma unroll
        for (int n = 0; n < 4; ++n) acc[m][n] = 0.0f;

    for (int kb = 0; kb < K; kb += 16) {
        __syncthreads();
#pragma unroll
        for (int j = 0; j < 2; ++j) {
            int f4 = t * 2 + j;
            int row = f4 >> 2;
            int c = f4 & 3;
            float4 av = *(const float4*)&A[(size_t)(bm + row) * lda + kb + c * 4];
            As[c * 4 + 0][row] = av.x; As[c * 4 + 1][row] = av.y;
            As[c * 4 + 2][row] = av.z; As[c * 4 + 3][row] = av.w;
            float4 bv = *(const float4*)&Bw[(size_t)(bn + row) * ldb + kb + c * 4];
            Bs[c * 4 + 0][row] = bv.x; Bs[c * 4 + 1][row] = bv.y;
            Bs[c * 4 + 2][row] = bv.z; Bs[c * 4 + 3][row] = bv.w;
        }
        __syncthreads();
#pragma unroll
        for (int k2 = 0; k2 < 16; ++k2) {
            float a[8];
#pragma unroll
            for (int m = 0; m < 8; ++m) a[m] = As[k2][ty * 8 + m];
            float4 bv = *(const float4*)&Bs[k2][tx * 4];
            float b4[4] = {bv.x, bv.y, bv.z, bv.w};
#pragma unroll
            for (int m = 0; m < 8; ++m)
#pragma unroll
                for (int n = 0; n < 4; ++n) acc[m][n] += a[m] * b4[n];
        }
    }

#pragma unroll
    for (int m = 0; m < 8; ++m) {
        int row = bm + ty * 8 + m;
#pragma unroll
        for (int n = 0; n < 4; ++n) {
            int col = bn + tx * 4 + n;
            float v = acc[m][n];
            if (bias) v += bias[col];
            if (act == 3) v = fmaxf(v, 0.0f);
            C[(size_t)row * N + col] = v;
        }
    }
}

template <int ACT>
__global__ void __launch_bounds__(128) gemm_nt(
    const float* __restrict__ A, int lda,
    const float* __restrict__ Bw, int ldb,
    const float* __restrict__ bias,
    float* __restrict__ C, int N, int K)
{
    gemm_core(A, lda, Bw, ldb, bias, C, N, K, blockIdx.x * 64, blockIdx.y * 64, ACT);
}

// ---------------- pre-phase: proj(600) | zero(400) | fc2 w2frag(192) ----------------
__global__ void __launch_bounds__(128) pre_all(
    const float* __restrict__ inputs,
    const float* __restrict__ ir_w, const float* __restrict__ ii_w, const float* __restrict__ in_w,
    const float* __restrict__ ir_b, const float* __restrict__ ii_b, const float* __restrict__ in_b,
    const float* __restrict__ fc2w)
{
    int bid = blockIdx.x;
    int t = threadIdx.x;
    if (bid < 600) {
        int z = bid / 200, rem = bid - z * 200;
        int bm = (rem % 50) * 64, bn = (rem / 50) * 64;
        const float* w = (z == 0) ? ir_w : (z == 1) ? ii_w : in_w;
        const float* b = (z == 0) ? ir_b : (z == 1) ? ii_b : in_b;
        float* C = g_scratch + ((z == 0) ? TR_OFF : (z == 1) ? TI_OFF : TN_OFF);
        gemm_core(inputs, NIN, w, NIN, b, C, NHID, NIN, bm, bn, 0);
    } else if (bid < 1000) {
        int b2 = bid - 600;
        float4* p = (float4*)(g_scratch + AGG_OFF) + (size_t)b2 * 512 + t * 4;
        float4 z4 = make_float4(0.f, 0.f, 0.f, 0.f);
#pragma unroll
        for (int j = 0; j < 4; ++j) p[j] = z4;
    } else {
        int b2 = bid - 1000;
        int p0 = (b2 * 128 + t) * 4;
#pragma unroll
        for (int j = 0; j < 4; ++j) {
            int p = p0 + j;
            int lane = p & 31;
            int reg = (p >> 5) & 1;
            int tile = (p >> 6) & 63;
            int kstep = tile & 1, ntile = tile >> 1;
            int c = (p >> 12) & 7;
            int kk = p >> 15;
            int n = ntile * 8 + (lane >> 2);
            int k = c * 32 + kstep * 16 + reg * 8 + (lane & 3) * 2;
            const float* w = fc2w + (size_t)(kk + 1) * 65536 + (size_t)n * 256 + k;
            g_wf[p] = pack_bf16(w[0], w[1]);
        }
    }
}

// ---------------- fc1 via bf16 mma: Hr/Hs -> g_hrhs (bf16) ----------------
__global__ void __launch_bounds__(512, 1) fc1_mma(
    const float* __restrict__ hidden,
    const float* __restrict__ fc1w,
    const float* __restrict__ fc1b)
{
    extern __shared__ uint32_t dsm[];
    uint32_t* As_w0 = dsm;
    uint32_t* Bs_w0 = dsm + EDGE_AS_WORDS;
    float* biasS = (float*)(dsm + EDGE_AS_WORDS + EDGE_BS_WORDS);

    int t = threadIdx.x;
    int wid = t >> 5, lid = t & 31;
    int m0 = blockIdx.x * 128;
    int kk = blockIdx.y, half = blockIdx.z, kt = kk + 1;

    if (t < 256) biasS[t] = half ? 0.0f : fc1b[kt * 256 + t];

    int grow = t >> 2, kq = t & 3;
    int kstep = kq >> 1, khalf = kq & 1;
    int mtile = grow >> 4, rl = grow & 15;
    uint32_t a_sts = (uint32_t)(((mtile * 2 + kstep) * 4) + (rl >> 3) + 2 * khalf) * 32
                     + (rl & 7) * 4;
    const float* Abase = hidden + (size_t)(m0 + grow) * 256 + kq * 8;

    int nn = t >> 1, kh = t & 1;
    const float* Bbase = fc1w + (size_t)kt * 131072 + (size_t)nn * 512 + half * 256 + kh * 16;
    int btile = (nn >> 3) * 2 + kh;
    uint32_t b_sts0 = (uint32_t)(btile * 2 + 0) * 32 + (nn & 7) * 4;
    uint32_t b_sts1 = (uint32_t)(btile * 2 + 1) * 32 + (nn & 7) * 4;

    int mw = wid >> 2, nw = wid & 3;

    float acc[2][8][4];
#pragma unroll
    for (int mt = 0; mt < 2; ++mt)
#pragma unroll
        for (int nt = 0; nt < 8; ++nt)
#pragma unroll
            for (int q = 0; q < 4; ++q) acc[mt][nt][q] = 0.0f;

    float4 av0, av1, bv0, bv1, bv2, bv3;

#define F1_LDG(c) do { \
        av0 = *(const float4*)(Abase + (c) * 32); \
        av1 = *(const float4*)(Abase + (c) * 32 + 4); \
        bv0 = *(const float4*)(Bbase + (c) * 32); \
        bv1 = *(const float4*)(Bbase + (c) * 32 + 4); \
        bv2 = *(const float4*)(Bbase + (c) * 32 + 8); \
        bv3 = *(const float4*)(Bbase + (c) * 32 + 12); \
    } while (0)

#define F1_STS(st) do { \
        uint4 xa; \
        xa.x = pack_bf16(av0.x, av0.y); xa.y = pack_bf16(av0.z, av0.w); \
        xa.z = pack_bf16(av1.x, av1.y); xa.w = pack_bf16(av1.z, av1.w); \
        *(uint4*)&As_w0[(st) * 2048 + a_sts] = xa; \
        uint4 w0, w1; \
        w0.x = pack_bf16(bv0.x, bv0.y); w0.y = pack_bf16(bv0.z, bv0.w); \
        w0.z = pack_bf16(bv1.x, bv1.y); w0.w = pack_bf16(bv1.z, bv1.w); \
        w1.x = pack_bf16(bv2.x, bv2.y); w1.y = pack_bf16(bv2.z, bv2.w); \
        w1.z = pack_bf16(bv3.x, bv3.y); w1.w = pack_bf16(bv3.z, bv3.w); \
        *(uint4*)&Bs_w0[(st) * 4096 + b_sts0] = w0; \
        *(uint4*)&Bs_w0[(st) * 4096 + b_sts1] = w1; \
    } while (0)

    F1_LDG(0);
    F1_STS(0);
    F1_LDG(1);

    for (int c = 0; c < 8; ++c) {
        int st = c & 1;
        __syncthreads();
        const uint32_t* Asb = As_w0 + st * 2048;
        const uint32_t* Bsb = Bs_w0 + st * 4096;
#pragma unroll
        for (int ks = 0; ks < 2; ++ks) {
            uint32_t a[2][4];
#pragma unroll
            for (int mt = 0; mt < 2; ++mt) {
                int tile = (mw * 2 + mt) * 2 + ks;
#pragma unroll
                for (int rg = 0; rg < 4; ++rg)
                    a[mt][rg] = Asb[(tile * 4 + rg) * 32 + lid];
            }
#pragma unroll
            for (int nt = 0; nt < 8; ++nt) {
                int tile = (nw * 8 + nt) * 2 + ks;
                uint32_t b0 = Bsb[(tile * 2 + 0) * 32 + lid];
                uint32_t b1 = Bsb[(tile * 2 + 1) * 32 + lid];
                mma_bf16(acc[0][nt], a[0], b0, b1);
                mma_bf16(acc[1][nt], a[1], b0, b1);
            }
        }
        if (c < 7) {
            F1_STS((c + 1) & 1);
            if (c < 6) F1_LDG(c + 2);
        }
    }

    int lq = lid & 3, lr = lid >> 2;
    uint32_t* outp = g_hrhs + (size_t)(kk * 2 + half) * HH_PLANE;
#pragma unroll
    for (int mt = 0; mt < 2; ++mt)
#pragma unroll
        for (int rh = 0; rh < 2; ++rh) {
            int row = m0 + mw * 32 + mt * 16 + rh * 8 + lr;
#pragma unroll
            for (int nt = 0; nt < 8; ++nt) {
                int col = nw * 64 + nt * 8 + lq * 2;
                float v0 = acc[mt][nt][rh * 2 + 0] + biasS[col];
                float v1 = acc[mt][nt][rh * 2 + 1] + biasS[col + 1];
                outp[(size_t)row * HH_ROW_WORDS + (col >> 1)] = pack_bf16(v0, v1);
            }
        }
#undef F1_LDG
#undef F1_STS
}

// ---------------- gate GEMMs via bf16 mma: agg @ {hr,hi,hh}^T -> fp32 scratch ----------------
// grid (25, 3). Same machinery as fc1_mma (ldb = 256, no bias, fp32 out).
__global__ void __launch_bounds__(512, 1) gate_mma(
    const float* __restrict__ hr_w, const float* __restrict__ hi_w, const float* __restrict__ hh_w)
{
    extern __shared__ uint32_t dsm[];
    uint32_t* As_w0 = dsm;
    uint32_t* Bs_w0 = dsm + EDGE_AS_WORDS;

    int t = threadIdx.x;
    int wid = t >> 5, lid = t & 31;
    int m0 = blockIdx.x * 128;
    int z = blockIdx.y;
    const float* W = (z == 0) ? hr_w : (z == 1) ? hi_w : hh_w;
    float* C = g_scratch + ((z == 0) ? GR_OFF : (z == 1) ? GI_OFF : GH_OFF);
    const float* A = g_scratch + AGG_OFF;

    int grow = t >> 2, kq = t & 3;
    int kstep = kq >> 1, khalf = kq & 1;
    int mtile = grow >> 4, rl = grow & 15;
    uint32_t a_sts = (uint32_t)(((mtile * 2 + kstep) * 4) + (rl >> 3) + 2 * khalf) * 32
                     + (rl & 7) * 4;
    const float* Abase = A + (size_t)(m0 + grow) * 256 + kq * 8;

    int nn = t >> 1, kh = t & 1;
    const float* Bbase = W + (size_t)nn * 256 + kh * 16;
    int btile = (nn >> 3) * 2 + kh;
    uint32_t b_sts0 = (uint32_t)(btile * 2 + 0) * 32 + (nn & 7) * 4;
    uint32_t b_sts1 = (uint32_t)(btile * 2 + 1) * 32 + (nn & 7) * 4;

    int mw = wid >> 2, nw = wid & 3;

    float acc[2][8][4];
#pragma unroll
    for (int mt = 0; mt < 2; ++mt)
#pragma unroll
        for (int nt = 0; nt < 8; ++nt)
#pragma unroll
            for (int q = 0; q < 4; ++q) acc[mt][nt][q] = 0.0f;

    float4 av0, av1, bv0, bv1, bv2, bv3;

#define G_LDG(c) do { \
        av0 = *(const float4*)(Abase + (c) * 32); \
        av1 = *(const float4*)(Abase + (c) * 32 + 4); \
        bv0 = *(const float4*)(Bbase + (c) * 32); \
        bv1 = *(const float4*)(Bbase + (c) * 32 + 4); \
        bv2 = *(const float4*)(Bbase + (c) * 32 + 8); \
        bv3 = *(const float4*)(Bbase + (c) * 32 + 12); \
    } while (0)

#define G_STS(st) do { \
        uint4 xa; \
        xa.x = pack_bf16(av0.x, av0.y); xa.y = pack_bf16(av0.z, av0.w); \
        xa.z = pack_bf16(av1.x, av1.y); xa.w = pack_bf16(av1.z, av1.w); \
        *(uint4*)&As_w0[(st) * 2048 + a_sts] = xa; \
        uint4 w0, w1; \
        w0.x = pack_bf16(bv0.x, bv0.y); w0.y = pack_bf16(bv0.z, bv0.w); \
        w0.z = pack_bf16(bv1.x, bv1.y); w0.w = pack_bf16(bv1.z, bv1.w); \
        w1.x = pack_bf16(bv2.x, bv2.y); w1.y = pack_bf16(bv2.z, bv2.w); \
        w1.z = pack_bf16(bv3.x, bv3.y); w1.w = pack_bf16(bv3.z, bv3.w); \
        *(uint4*)&Bs_w0[(st) * 4096 + b_sts0] = w0; \
        *(uint4*)&Bs_w0[(st) * 4096 + b_sts1] = w1; \
    } while (0)

    G_LDG(0);
    G_STS(0);
    G_LDG(1);

    for (int c = 0; c < 8; ++c) {
        int st = c & 1;
        __syncthreads();
        const uint32_t* Asb = As_w0 + st * 2048;
        const uint32_t* Bsb = Bs_w0 + st * 4096;
#pragma unroll
        for (int ks = 0; ks < 2; ++ks) {
            uint32_t a[2][4];
#pragma unroll
            for (int mt = 0; mt < 2; ++mt) {
                int tile = (mw * 2 + mt) * 2 + ks;
#pragma unroll
                for (int rg = 0; rg < 4; ++rg)
                    a[mt][rg] = Asb[(tile * 4 + rg) * 32 + lid];
            }
#pragma unroll
            for (int nt = 0; nt < 8; ++nt) {
                int tile = (nw * 8 + nt) * 2 + ks;
                uint32_t b0 = Bsb[(tile * 2 + 0) * 32 + lid];
                uint32_t b1 = Bsb[(tile * 2 + 1) * 32 + lid];
                mma_bf16(acc[0][nt], a[0], b0, b1);
                mma_bf16(acc[1][nt], a[1], b0, b1);
            }
        }
        if (c < 7) {
            G_STS((c + 1) & 1);
            if (c < 6) G_LDG(c + 2);
        }
    }

    int lq = lid & 3, lr = lid >> 2;
#pragma unroll
    for (int mt = 0; mt < 2; ++mt)
#pragma unroll
        for (int rh = 0; rh < 2; ++rh) {
            int row = m0 + mw * 32 + mt * 16 + rh * 8 + lr;
#pragma unroll
            for (int nt = 0; nt < 8; ++nt) {
                int col = nw * 64 + nt * 8 + lq * 2;
                C[(size_t)row * 256 + col]     = acc[mt][nt][rh * 2 + 0];
                C[(size_t)row * 256 + col + 1] = acc[mt][nt][rh * 2 + 1];
            }
        }
#undef G_LDG
#undef G_STS
}

// ---------------- GRU elementwise ----------------
__global__ void gru_elem(const float* __restrict__ hidden, float* __restrict__ new_hidden) {
    const float* tr = g_scratch + TR_OFF;
    const float* ti = g_scratch + TI_OFF;
    const float* tn = g_scratch + TN_OFF;
    const float* gr = g_scratch + GR_OFF;
    const float* gi = g_scratch + GI_OFF;
    const float* gh = g_scratch + GH_OFF;
    int total = BATCH * NVARS * NHID;
    for (int idx = blockIdx.x * blockDim.x + threadIdx.x; idx < total; idx += gridDim.x * blockDim.x) {
        float r_ = sigm(gr[idx] + tr[idx]);
        float i_ = sigm(gi[idx] + ti[idx]);
        float n_ = tanha(tn[idx] + r_ * gh[idx]);
        new_hidden[idx] = (1.0f - i_) * n_ + i_ * hidden[idx];
    }
}

// ---------------- head GEMM via split-bf16 (3-MMA) ----------------
// grid (25): C[128x256] = relu(A[128x256] @ W[256x256]^T + bias), near-fp32 accuracy.
__global__ void __launch_bounds__(512, 1) head_mma(
    const float* __restrict__ Ain, const float* __restrict__ W,
    const float* __restrict__ bias, float* __restrict__ C)
{
    extern __shared__ uint32_t dsm[];
    uint32_t* Ahi = dsm;
    uint32_t* Alo = dsm + 2048;
    uint32_t* Bhi = dsm + 4096;
    uint32_t* Blo = dsm + 8192;
    float* biasS = (float*)(dsm + 12288);

    int t = threadIdx.x;
    int wid = t >> 5, lid = t & 31;
    int m0 = blockIdx.x * 128;

    if (t < 256) biasS[t] = bias[t];

    int grow = t >> 2, kq = t & 3;
    int kstep = kq >> 1, khalf = kq & 1;
    int mtile = grow >> 4, rl = grow & 15;
    uint32_t a_sts = (uint32_t)(((mtile * 2 + kstep) * 4) + (rl >> 3) + 2 * khalf) * 32
                     + (rl & 7) * 4;
    const float* Abase = Ain + (size_t)(m0 + grow) * 256 + kq * 8;

    int nn = t >> 1, kh = t & 1;
    const float* Bbase = W + (size_t)nn * 256 + kh * 16;
    int btile = (nn >> 3) * 2 + kh;
    uint32_t b_sts0 = (uint32_t)(btile * 2 + 0) * 32 + (nn & 7) * 4;
    uint32_t b_sts1 = (uint32_t)(btile * 2 + 1) * 32 + (nn & 7) * 4;

    int mw = wid >> 2, nw = wid & 3;

    float acc[2][8][4];
#pragma unroll
    for (int mt = 0; mt < 2; ++mt)
#pragma unroll
        for (int nt = 0; nt < 8; ++nt)
#pragma unroll
            for (int q = 0; q < 4; ++q) acc[mt][nt][q] = 0.0f;

    float4 av0, av1, bv0, bv1, bv2, bv3;

#define H_LDG(c) do { \
        av0 = *(const float4*)(Abase + (c) * 32); \
        av1 = *(const float4*)(Abase + (c) * 32 + 4); \
        bv0 = *(const float4*)(Bbase + (c) * 32); \
        bv1 = *(const float4*)(Bbase + (c) * 32 + 4); \
        bv2 = *(const float4*)(Bbase + (c) * 32 + 8); \
        bv3 = *(const float4*)(Bbase + (c) * 32 + 12); \
    } while (0)

#define H_STS() do { \
        uint4 xh, xl; \
        split_bf16(av0.x, av0.y, xh.x, xl.x); \
        split_bf16(av0.z, av0.w, xh.y, xl.y); \
        split_bf16(av1.x, av1.y, xh.z, xl.z); \
        split_bf16(av1.z, av1.w, xh.w, xl.w); \
        *(uint4*)&Ahi[a_sts] = xh; \
        *(uint4*)&Alo[a_sts] = xl; \
        uint4 wh0, wl0, wh1, wl1; \
        split_bf16(bv0.x, bv0.y, wh0.x, wl0.x); \
        split_bf16(bv0.z, bv0.w, wh0.y, wl0.y); \
        split_bf16(bv1.x, bv1.y, wh0.z, wl0.z); \
        split_bf16(bv1.z, bv1.w, wh0.w, wl0.w); \
        split_bf16(bv2.x, bv2.y, wh1.x, wl1.x); \
        split_bf16(bv2.z, bv2.w, wh1.y, wl1.y); \
        split_bf16(bv3.x, bv3.y, wh1.z, wl1.z); \
        split_bf16(bv3.z, bv3.w, wh1.w, wl1.w); \
        *(uint4*)&Bhi[b_sts0] = wh0; \
        *(uint4*)&Blo[b_sts0] = wl0; \
        *(uint4*)&Bhi[b_sts1] = wh1; \
        *(uint4*)&Blo[b_sts1] = wl1; \
    } while (0)

    H_LDG(0);

    for (int c = 0; c < 8; ++c) {
        __syncthreads();
        H_STS();
        __syncthreads();
        if (c < 7) H_LDG(c + 1);
#pragma unroll
        for (int ks = 0; ks < 2; ++ks) {
            uint32_t ah[2][4], al[2][4];
#pragma unroll
            for (int mt = 0; mt < 2; ++mt) {
                int tile = (mw * 2 + mt) * 2 + ks;
#pragma unroll
                for (int rg = 0; rg < 4; ++rg) {
                    ah[mt][rg] = Ahi[(tile * 4 + rg) * 32 + lid];
                    al[mt][rg] = Alo[(tile * 4 + rg) * 32 + lid];
                }
            }
#pragma unroll
            for (int nt = 0; nt < 8; ++nt) {
                int tile = (nw * 8 + nt) * 2 + ks;
                uint32_t bh0 = Bhi[(tile * 2 + 0) * 32 + lid];
                uint32_t bh1 = Bhi[(tile * 2 + 1) * 32 + lid];
                uint32_t bl0 = Blo[(tile * 2 + 0) * 32 + lid];
                uint32_t bl1 = Blo[(tile * 2 + 1) * 32 + lid];
#pragma unroll
                for (int mt = 0; mt < 2; ++mt) {
                    mma_bf16(acc[mt][nt], ah[mt], bh0, bh1);
                    mma_bf16(acc[mt][nt], ah[mt], bl0, bl1);
                    mma_bf16(acc[mt][nt], al[mt], bh0, bh1);
                }
            }
        }
    }

    int lq = lid & 3, lr = lid >> 2;
#pragma unroll
    for (int mt = 0; mt < 2; ++mt)
#pragma unroll
        for (int rh = 0; rh < 2; ++rh) {
            int row = m0 + mw * 32 + mt * 16 + rh * 8 + lr;
#pragma unroll
            for (int nt = 0; nt < 8; ++nt) {
                int col = nw * 64 + nt * 8 + lq * 2;
                float v0 = fmaxf(acc[mt][nt][rh * 2 + 0] + biasS[col], 0.0f);
                float v1 = fmaxf(acc[mt][nt][rh * 2 + 1] + biasS[col + 1], 0.0f);
                C[(size_t)row * 256 + col]     = v0;
                C[(size_t)row * 256 + col + 1] = v1;
            }
        }
#undef H_LDG
#undef H_STS
}

// ---------------- bf16 mma.sync edge kernel ----------------
__global__ void __launch_bounds__(512, 1) edge_mma(
    const float* __restrict__ edges,
    const float* __restrict__ fc2b)
{
    extern __shared__ uint32_t dsm[];
    uint32_t* As_w0 = dsm;
    uint32_t* Bs_w0 = dsm + EDGE_AS_WORDS;
    float* biasS = (float*)(dsm + EDGE_AS_WORDS + EDGE_BS_WORDS);

    int t = threadIdx.x;
    int wid = t >> 5, lid = t & 31;
    int m0 = blockIdx.x * 128;
    int r = blockIdx.y;
    int kk = blockIdx.z, kt = kk + 1;

    const uint32_t* HRw = g_hrhs + (size_t)(kk * 2 + 0) * HH_PLANE;
    const uint32_t* HSw = g_hrhs + (size_t)(kk * 2 + 1) * HH_PLANE;

    if (t < 256) biasS[t] = fc2b[kt * 256 + t];

    int grow = t >> 2, kq = t & 3;
    int kstep = kq >> 1, khalf = kq & 1;
    int gg = m0 + grow;
    int gb = gg / 50, gi = gg - gb * 50;
    uint32_t hr_base = (uint32_t)(gb * 50 + r) * HH_ROW_WORDS + kq * 4;
    uint32_t hs_base = (uint32_t)(gb * 50 + gi) * HH_ROW_WORDS + kq * 4;
    int mtile = grow >> 4, rl = grow & 15;
    uint32_t a_sts = (uint32_t)(((mtile * 2 + kstep) * 4) + (rl >> 3) + 2 * khalf) * 32
                     + (rl & 7) * 4;
    const uint32_t* wf = g_wf + (size_t)kk * 32768 + t * 8;

    int mw = wid >> 2, nw = wid & 3;

    float acc[2][8][4];
#pragma unroll
    for (int mt = 0; mt < 2; ++mt)
#pragma unroll
        for (int nt = 0; nt < 8; ++nt)
#pragma unroll
            for (int q = 0; q < 4; ++q) acc[mt][nt][q] = 0.0f;

    uint4 hv, sv, wv0, wv1;

#define LDG_CHUNK(c) do { \
        hv = *(const uint4*)(HRw + hr_base + (c) * 16); \
        sv = *(const uint4*)(HSw + hs_base + (c) * 16); \
        wv0 = *(const uint4*)(wf + (c) * 4096); \
        wv1 = *(const uint4*)(wf + (c) * 4096 + 4); \
    } while (0)

#define STS_CHUNK(st) do { \
        uint4 xa; \
        xa.x = tanh_bf16x2(add_bf16x2(hv.x, sv.x)); \
        xa.y = tanh_bf16x2(add_bf16x2(hv.y, sv.y)); \
        xa.z = tanh_bf16x2(add_bf16x2(hv.z, sv.z)); \
        xa.w = tanh_bf16x2(add_bf16x2(hv.w, sv.w)); \
        *(uint4*)&As_w0[(st) * 2048 + a_sts] = xa; \
        *(uint4*)&Bs_w0[(st) * 4096 + t * 8] = wv0; \
        *(uint4*)&Bs_w0[(st) * 4096 + t * 8 + 4] = wv1; \
    } while (0)

    LDG_CHUNK(0);
    STS_CHUNK(0);
    LDG_CHUNK(1);

    for (int c = 0; c < 8; ++c) {
        int st = c & 1;
        __syncthreads();
        const uint32_t* Asb = As_w0 + st * 2048;
        const uint32_t* Bsb = Bs_w0 + st * 4096;
#pragma unroll
        for (int ks = 0; ks < 2; ++ks) {
            uint32_t a[2][4];
#pragma unroll
            for (int mt = 0; mt < 2; ++mt) {
                int tile = (mw * 2 + mt) * 2 + ks;
#pragma unroll
                for (int rg = 0; rg < 4; ++rg)
                    a[mt][rg] = Asb[(tile * 4 + rg) * 32 + lid];
            }
#pragma unroll
            for (int nt = 0; nt < 8; ++nt) {
                int tile = (nw * 8 + nt) * 2 + ks;
                uint32_t b0 = Bsb[(tile * 2 + 0) * 32 + lid];
                uint32_t b1 = Bsb[(tile * 2 + 1) * 32 + lid];
                mma_bf16(acc[0][nt], a[0], b0, b1);
                mma_bf16(acc[1][nt], a[1], b0, b1);
            }
        }
        if (c < 7) {
            STS_CHUNK((c + 1) & 1);
            if (c < 6) LDG_CHUNK(c + 2);
        }
    }

    int lq = lid & 3, lr = lid >> 2;
    int base_row = mw * 32;
    int bfirst = (m0 + base_row) / 50;
    int blast = (m0 + base_row + 31) / 50;
    int has1 = (blast != bfirst);

    float wgt[4];
    int sg[4];
#pragma unroll
    for (int j = 0; j < 4; ++j) {
        int mt = j >> 1, rh = j & 1;
        int row_local = base_row + mt * 16 + rh * 8 + lr;
        int g = m0 + row_local;
        int b = g / 50, i = g - b * 50;
        sg[j] = b - bfirst;
        float w = 0.0f;
        if (i != r) {
            int e = i * 49 + r - (i < r ? 1 : 0);
            w = __ldg(&edges[((size_t)b * NEDGE + e) * 4 + kt]) * (1.0f / 147.0f);
        }
        wgt[j] = w;
    }

    float* agg0 = g_scratch + AGG_OFF + ((size_t)(bfirst * 50 + r)) * 256;

#pragma unroll
    for (int nt = 0; nt < 8; ++nt) {
        int colg = nw * 64 + nt * 8 + lq * 2;
        float b0 = biasS[colg], b1 = biasS[colg + 1];
        float c0[2] = {0.0f, 0.0f}, c1[2] = {0.0f, 0.0f};
#pragma unroll
        for (int j = 0; j < 4; ++j) {
            int mt = j >> 1, rh = j & 1;
            float t0 = tanha(acc[mt][nt][rh * 2 + 0] + b0) * wgt[j];
            float t1 = tanha(acc[mt][nt][rh * 2 + 1] + b1) * wgt[j];
            if (sg[j] == 0) { c0[0] += t0; c1[0] += t1; }
            else            { c0[1] += t0; c1[1] += t1; }
        }
#pragma unroll
        for (int o = 4; o <= 16; o <<= 1) {
            c0[0] += __shfl_xor_sync(0xffffffffu, c0[0], o);
            c1[0] += __shfl_xor_sync(0xffffffffu, c1[0], o);
            if (has1) {
                c0[1] += __shfl_xor_sync(0xffffffffu, c0[1], o);
                c1[1] += __shfl_xor_sync(0xffffffffu, c1[1], o);
            }
        }
        if (lid < 4) {
            atomicAdd(&agg0[colg], c0[0]);
            atomicAdd(&agg0[colg + 1], c1[0]);
            if (has1) {
                atomicAdd(&agg0[12800 + colg], c0[1]);
                atomicAdd(&agg0[12800 + colg + 1], c1[1]);
            }
        }
    }
#undef LDG_CHUNK
#undef STS_CHUNK
}

// ---------------- launch ----------------
extern "C" void kernel_launch(void* const* d_in, const int* in_sizes, int n_in,
                              void* d_out, int out_size) {
    const float* inputs = (const float*)d_in[0];
    const float* hidden = (const float*)d_in[1];
    const float* edges  = (const float*)d_in[2];
    const float* fc1w   = (const float*)d_in[3];
    const float* fc1b   = (const float*)d_in[4];
    const float* fc2w   = (const float*)d_in[5];
    const float* fc2b   = (const float*)d_in[6];
    const float* hr_w   = (const float*)d_in[7];
    const float* hi_w   = (const float*)d_in[8];
    const float* hh_w   = (const float*)d_in[9];
    const float* ir_w   = (const float*)d_in[10];
    const float* ir_b   = (const float*)d_in[11];
    const float* ii_w   = (const float*)d_in[12];
    const float* ii_b   = (const float*)d_in[13];
    const float* in_w   = (const float*)d_in[14];
    const float* in_b   = (const float*)d_in[15];
    const float* of1_w  = (const float*)d_in[16];
    const float* of1_b  = (const float*)d_in[17];
    const float* of2_w  = (const float*)d_in[18];
    const float* of2_b  = (const float*)d_in[19];
    const float* mu_w   = (const float*)d_in[20];
    const float* mu_b   = (const float*)d_in[21];

    float* out = (float*)d_out;
    float* out_mu   = out;               // [64,50,64]
    float* out_nh   = out + 204800;      // [64,50,256]
    float* out_pred = out + 1024000;     // [64,50,256]

    float* S = nullptr;
    cudaGetSymbolAddress((void**)&S, g_scratch);

    cudaFuncSetAttribute(edge_mma, cudaFuncAttributeMaxDynamicSharedMemorySize, EDGE_SMEM_BYTES);
    cudaFuncSetAttribute(fc1_mma, cudaFuncAttributeMaxDynamicSharedMemorySize, EDGE_SMEM_BYTES);
    cudaFuncSetAttribute(gate_mma, cudaFuncAttributeMaxDynamicSharedMemorySize, EDGE_SMEM_BYTES);
    cudaFuncSetAttribute(head_mma, cudaFuncAttributeMaxDynamicSharedMemorySize, HEAD_SMEM_BYTES);

    const int M = BATCH * NVARS;  // 3200

    fc1_mma<<<dim3(25, 3, 2), 512, EDGE_SMEM_BYTES>>>(hidden, fc1w, fc1b);
    pre_all<<<1192, 128>>>(inputs, ir_w, ii_w, in_w, ir_b, ii_b, in_b, fc2w);

    edge_mma<<<dim3(25, NVARS, 3), 512, EDGE_SMEM_BYTES>>>(edges, fc2b);

    gate_mma<<<dim3(25, 3), 512, EDGE_SMEM_BYTES>>>(hr_w, hi_w, hh_w);
    gru_elem<<<800, 256>>>(hidden, out_nh);

    head_mma<<<25, 512, HEAD_SMEM_BYTES>>>(out_nh, of1_w, of1_b, S + P1_OFF);
    head_mma<<<25, 512, HEAD_SMEM_BYTES>>>(S + P1_OFF, of2_w, of2_b, out_pred);

    gemm_nt<0><<<dim3(M / 64, 1), 128>>>(out_pred, NHID, mu_w, NHID, mu_b, out_mu, NIN, NHID);
}